// round 12
// baseline (speedup 1.0000x reference)
#include <cuda_runtime.h>
#include <math_constants.h>

#define BB 2
#define NN 8192
#define SS 4096
#define IN_CH 64
#define TRANS_CH 64
#define OUT_CH 128
#define TP 16         // sampled points per block in fused kernel

typedef unsigned long long u64;

// ---------------- device scratch (no cudaMalloc allowed) ----------------
__device__ float4 g_xyzw[BB * NN];      // x,y,z,|x|^2
__device__ u64    g_keys2[BB * NN];     // sorted keys
__device__ int    g_srank[BB * NN];     // sorted pos -> s+1 (0 = not sampled)
__device__ int    g_ccnt[BB * 32];      // members per 256-chunk

// z-sorted full set + compacted sampled subset
__device__ float4 g_pfull[BB * NN];
__device__ float  g_zfull[BB * NN];
__device__ int    g_ofull[BB * NN];     // sorted pos -> original global id
__device__ float4 g_psamp[BB * SS];
__device__ float  g_zsamp[BB * SS];
__device__ int    g_osamp[BB * SS];     // sorted pos -> sample-space pos

// KNN results, keyed by SAMPLE-SPACE position s
__device__ int    g_aidx[BB * SS * 4];
__device__ float  g_adist[BB * SS * 4];
__device__ int    g_saidx[BB * SS * 4];
__device__ float  g_sadist[BB * SS * 4];

// ---------------- helpers ----------------
__device__ __forceinline__ void insert4f(float (&bd)[4], int (&bi)[4], float d, int j) {
    if (d >= bd[3]) return;
    if (d < bd[2]) {
        bd[3] = bd[2]; bi[3] = bi[2];
        if (d < bd[1]) {
            bd[2] = bd[1]; bi[2] = bi[1];
            if (d < bd[0]) {
                bd[1] = bd[0]; bi[1] = bi[0];
                bd[0] = d; bi[0] = j;
            } else { bd[1] = d; bi[1] = j; }
        } else { bd[2] = d; bi[2] = j; }
    } else { bd[3] = d; bi[3] = j; }
}

__device__ __forceinline__ u64 zkey(float z, unsigned idx) {
    unsigned bits = __float_as_uint(z);
    bits = (bits & 0x80000000u) ? ~bits : (bits | 0x80000000u);
    return ((u64)bits << 32) | idx;
}

// compare-exchange primitives (keys are UNIQUE -> min/max == network swap)
__device__ __forceinline__ void cmp_swap_pair(u64& lo, u64& hi, bool up) {
    u64 mn = lo < hi ? lo : hi;
    u64 mx = lo < hi ? hi : lo;
    lo = up ? mn : mx;
    hi = up ? mx : mn;
}
__device__ __forceinline__ u64 shfl_cmp(u64 v, int gi, int j, int k) {
    u64 o = __shfl_xor_sync(0xffffffffu, v, j);
    bool keepmin = (((gi & j) == 0) == ((gi & k) == 0));
    u64 mn = v < o ? v : o, mx = v < o ? o : v;
    return keepmin ? mn : mx;
}

// one bitonic stage k restricted to j<=128, on a warp-owned block of 256
// contiguous elements held as r[m] = elem(gbase + m*32 + lane)
__device__ __forceinline__ void reg_stage8(u64 (&r)[8], int gbase, int lane, int k) {
    // in-thread passes j = 128, 64, 32 (partner = other register, same lane)
    #pragma unroll
    for (int j = 128; j >= 32; j >>= 1) {
        if (j <= (k >> 1)) {
            const int jm = j >> 5;
            #pragma unroll
            for (int m = 0; m < 8; m++) {
                if ((m & jm) == 0) {
                    int gi = gbase + (m << 5) + lane;
                    cmp_swap_pair(r[m], r[m + jm], ((gi & k) == 0));
                }
            }
        }
    }
    // shuffle passes j = 16..1
    #pragma unroll
    for (int j = 16; j >= 1; j >>= 1) {
        if (j <= (k >> 1)) {
            #pragma unroll
            for (int m = 0; m < 8; m++)
                r[m] = shfl_cmp(r[m], gbase + (m << 5) + lane, j, k);
        }
    }
}

// ---------------- K0: fused prep + sampled_xyz gather ----------------
__global__ void k_prep_gather(const float* __restrict__ xyz,
                              const int*   __restrict__ sample,
                              float* __restrict__ out) {
    int i = blockIdx.x * blockDim.x + threadIdx.x;
    if (i < BB * NN) {
        float x = xyz[3 * i], y = xyz[3 * i + 1], z = xyz[3 * i + 2];
        float sq = fmaf(x, x, fmaf(y, y, z * z));
        g_xyzw[i] = make_float4(x, y, z, sq);
    } else {
        int j = i - BB * NN;
        if (j >= BB * SS) return;
        int b = j / SS;
        int g = sample[j];
        const float* p = xyz + 3 * (b * NN + g);
        out[3 * j + 0] = p[0];
        out[3 * j + 1] = p[1];
        out[3 * j + 2] = p[2];
    }
}

// ---------------- K1: whole-batch bitonic sort in ONE kernel ----------------
// grid = BB, 1024 threads, 64KB dynamic smem (all 8192 keys resident).
// Warp owns 256 contiguous elements in registers; smem only for j>=256.
__global__ __launch_bounds__(1024) void k_sort_all(const float* __restrict__ xyz) {
    extern __shared__ u64 sk[];               // [NN]
    const int b = blockIdx.x;
    const int t = threadIdx.x, lane = t & 31, w = t >> 5;
    const int gbase = w << 8;                 // warp's 256-element block

    for (int i = t; i < NN; i += 1024)
        sk[i] = zkey(xyz[3 * (b * NN + i) + 2], (unsigned)i);
    __syncthreads();

    u64 r[8];
    #pragma unroll
    for (int m = 0; m < 8; m++) r[m] = sk[gbase + (m << 5) + lane];

    // stages k = 2..256: zero syncs
    #pragma unroll
    for (int k = 2; k <= 256; k <<= 1)
        reg_stage8(r, gbase, lane, k);

    // stages k = 512..8192: smem passes for j>=256, register tail j<=128
    #pragma unroll
    for (int k = 512; k <= 8192; k <<= 1) {
        __syncthreads();
        #pragma unroll
        for (int m = 0; m < 8; m++) sk[gbase + (m << 5) + lane] = r[m];
        __syncthreads();
        for (int j = k >> 1; j >= 256; j >>= 1) {
            #pragma unroll
            for (int i = t; i < NN; i += 1024) {
                int p = i ^ j;
                if (p > i) {
                    u64 x = sk[i], y = sk[p];
                    bool up = ((i & k) == 0);
                    if ((x > y) == up) { sk[i] = y; sk[p] = x; }
                }
            }
            __syncthreads();
        }
        #pragma unroll
        for (int m = 0; m < 8; m++) r[m] = sk[gbase + (m << 5) + lane];
        reg_stage8(r, gbase, lane, k);
    }

    #pragma unroll
    for (int m = 0; m < 8; m++)
        g_keys2[b * NN + gbase + (m << 5) + lane] = r[m];
}

// ---------------- compaction pass 1: full scatter + membership + chunk counts ----------------
__global__ __launch_bounds__(256) void k_scatter_full(const int* __restrict__ sample) {
    const int i = blockIdx.x * 256 + threadIdx.x;   // index in [0, BB*NN)
    const int b = i / NN;
    const int lane = threadIdx.x & 31, wid = threadIdx.x >> 5;

    u64 key = g_keys2[i];
    int g = (int)(key & 0xffffffffu);
    float4 v = g_xyzw[b * NN + g];
    g_pfull[i] = v;
    g_zfull[i] = v.z;
    g_ofull[i] = g;

    // membership: binary search in sorted sample[b]
    const int* sm = sample + b * SS;
    int lo = 0, hi = SS;
    while (lo < hi) { int mid = (lo + hi) >> 1; if (sm[mid] < g) lo = mid + 1; else hi = mid; }
    int s = (lo < SS && sm[lo] == g) ? (lo + 1) : 0;
    g_srank[i] = s;

    unsigned bal = __ballot_sync(0xffffffffu, s > 0);
    __shared__ int ws[8];
    if (lane == 0) ws[wid] = __popc(bal);
    __syncthreads();
    if (threadIdx.x == 0) {
        int tot = 0;
        #pragma unroll
        for (int w = 0; w < 8; w++) tot += ws[w];
        g_ccnt[blockIdx.x] = tot;
    }
}

// ---------------- compaction pass 2: rank + scatter sampled subset ----------------
__global__ __launch_bounds__(256) void k_scatter_samp() {
    const int i = blockIdx.x * 256 + threadIdx.x;
    const int b = i / NN;
    const int c = blockIdx.x & 31;                  // chunk within batch (32 per batch)
    const int lane = threadIdx.x & 31, wid = threadIdx.x >> 5;

    int s = g_srank[i];
    bool m = (s > 0);

    unsigned bal = __ballot_sync(0xffffffffu, m);
    int lrank = __popc(bal & ((1u << lane) - 1u));
    __shared__ int ws[8];
    __shared__ int coff;
    if (lane == 0) ws[wid] = __popc(bal);
    if (wid == 0) {                                 // prefix over preceding chunks
        int v = (lane < c) ? g_ccnt[b * 32 + lane] : 0;
        #pragma unroll
        for (int off = 16; off; off >>= 1) v += __shfl_xor_sync(0xffffffffu, v, off);
        if (lane == 0) coff = v;
    }
    __syncthreads();
    int woff = 0;
    #pragma unroll
    for (int w = 0; w < 8; w++) if (w < wid) woff += ws[w];

    if (m) {
        u64 key = g_keys2[i];
        int g = (int)(key & 0xffffffffu);
        int pos = coff + woff + lrank;
        float4 v = g_xyzw[b * NN + g];
        g_psamp[b * SS + pos] = v;
        g_zsamp[b * SS + pos] = v.z;
        g_osamp[b * SS + pos] = s - 1;
    }
}

// ---------------- KNN: pruned two-sided scan, 64-wide, lazy lane-local threshold ----------------
// (round-9 proven version; in-loop full merges measured 56us SLOWER in round 10)
__global__ __launch_bounds__(256) void k_knn() {
    const bool FULLV = (blockIdx.z == 0);
    const int b    = blockIdx.y;
    const int warp = threadIdx.x >> 5;
    const int lane = threadIdx.x & 31;
    const int r    = blockIdx.x * 8 + warp;      // rank in z-sorted sampled array

    const int M = FULLV ? NN : SS;
    const float4* pts = FULLV ? (g_pfull + b * NN) : (g_psamp + b * SS);
    const float*  zz  = FULLV ? (g_zfull + b * NN) : (g_zsamp + b * SS);
    const float4  qp  = g_psamp[b * SS + r];

    int start;
    if (FULLV) {
        int lo = 0, hi = NN;
        while (lo < hi) { int mid = (lo + hi) >> 1; if (zz[mid] < qp.z) lo = mid + 1; else hi = mid; }
        start = lo;
    } else {
        start = r;
    }

    float bd[4] = {CUDART_INF_F, CUDART_INF_F, CUDART_INF_F, CUDART_INF_F};
    int   bi[4] = {0, 0, 0, 0};
    float thr = CUDART_INF_F;

    int ptrL = start, ptrR = start;
    while (true) {
        bool canL = ptrL > 0, canR = ptrR < M;
        if (!canL && !canR) break;
        float dzL = canL ? (qp.z - zz[ptrL - 1]) : CUDART_INF_F;
        float dzR = canR ? (zz[ptrR] - qp.z)     : CUDART_INF_F;
        float mdz = fminf(dzL, dzR);
        if (mdz * mdz > thr) break;
        int i0, i1;
        if (dzR <= dzL) { i0 = ptrR + lane; i1 = i0 + 32; ptrR += 64; }
        else            { i0 = ptrL - 64 + lane; i1 = i0 + 32; ptrL -= 64; }
        bool changed = false;
        if (i0 >= 0 && i0 < M) {
            float4 c = pts[i0];
            float dot = fmaf(qp.x, c.x, fmaf(qp.y, c.y, qp.z * c.z));
            float d2  = fmaxf(qp.w + c.w - 2.0f * dot, 1e-12f);
            changed |= (d2 < bd[3]);
            insert4f(bd, bi, d2, i0);
        }
        if (i1 >= 0 && i1 < M) {
            float4 c = pts[i1];
            float dot = fmaf(qp.x, c.x, fmaf(qp.y, c.y, qp.z * c.z));
            float d2  = fmaxf(qp.w + c.w - 2.0f * dot, 1e-12f);
            changed |= (d2 < bd[3]);
            insert4f(bd, bi, d2, i1);
        }
        if (__any_sync(0xffffffffu, changed)) {
            float tt = bd[3];
            #pragma unroll
            for (int off = 16; off; off >>= 1)
                tt = fminf(tt, __shfl_xor_sync(0xffffffffu, tt, off));
            thr = tt;
        }
    }

    #pragma unroll
    for (int off = 16; off; off >>= 1) {
        float od[4]; int oi[4];
        #pragma unroll
        for (int k = 0; k < 4; k++) {
            od[k] = __shfl_xor_sync(0xffffffffu, bd[k], off);
            oi[k] = __shfl_xor_sync(0xffffffffu, bi[k], off);
        }
        #pragma unroll
        for (int k = 0; k < 4; k++) insert4f(bd, bi, od[k], oi[k]);
    }

    if (lane == 0) {
        int s = g_osamp[b * SS + r];
        if (FULLV) {
            #pragma unroll
            for (int k = 0; k < 4; k++) {
                g_aidx [(b * SS + s) * 4 + k] = g_ofull[b * NN + bi[k]];
                g_adist[(b * SS + s) * 4 + k] = sqrtf(bd[k]);
            }
        } else {
            #pragma unroll
            for (int k = 0; k < 4; k++) {
                g_saidx [(b * SS + s) * 4 + k] = g_osamp[b * SS + bi[k]];
                g_sadist[(b * SS + s) * 4 + k] = sqrtf(bd[k]);
            }
        }
    }
}

// ---------------- fused 28-feature build + 3-layer MLP (TP=16, float4 smem reads) ----------------
__global__ __launch_bounds__(128) void k_fused(
    const float* __restrict__ feature,
    const int*   __restrict__ sample,
    const float* __restrict__ w1, const float* __restrict__ b1,
    const float* __restrict__ g1, const float* __restrict__ be1,
    const float* __restrict__ w2, const float* __restrict__ b2,
    const float* __restrict__ g2, const float* __restrict__ be2,
    const float* __restrict__ w3, const float* __restrict__ b3,
    const float* __restrict__ g3, const float* __restrict__ be3,
    float* __restrict__ out)
{
    __shared__ float x28[TP][28];
    __shared__ float t1s[TP][64];
    __shared__ float in2[TP][128];
    __shared__ int sp_g[TP];
    __shared__ int sp_a[TP][4];
    __shared__ int sp_ga[TP][4];

    const int tid = threadIdx.x;
    const int blk = blockIdx.x;
    const int b   = blk / (SS / TP);
    const int s0  = (blk % (SS / TP)) * TP;

    if (tid < TP) {
        int p = tid;
        int s = s0 + p;
        int g = sample[b * SS + s];
        sp_g[p] = g;
        #pragma unroll
        for (int k = 0; k < 4; k++) {
            sp_a[p][k] = g_aidx[(b * SS + s) * 4 + k];
            int sa = g_saidx[(b * SS + s) * 4 + k];
            sp_ga[p][k] = sample[b * SS + sa];
        }
        #pragma unroll
        for (int k = 0; k < 3; k++) {
            x28[p][k]     = g_adist[(b * SS + s) * 4 + 1 + k];
            x28[p][6 + k] = g_sadist[(b * SS + s) * 4 + 1 + k];
        }
    }
    __syncthreads();

    for (int t = tid; t < TP * 22; t += 128) {
        int p = t / 22, w = t % 22;
        int ia, ib, ch;
        if (w < 3) {
            int pi = (w < 2) ? 1 : 2;
            int pj = (w == 0) ? 2 : 3;
            ia = sp_a[p][pi]; ib = sp_a[p][pj]; ch = 3 + w;
        } else if (w < 6) {
            int u = w - 3;
            int pi = (u < 2) ? 1 : 2;
            int pj = (u == 0) ? 2 : 3;
            ia = sp_ga[p][pi]; ib = sp_ga[p][pj]; ch = 9 + u;
        } else {
            int u = w - 6;
            int i = u >> 2, j = u & 3;
            ia = sp_a[p][i]; ib = sp_ga[p][j]; ch = 12 + u;
        }
        float4 pa = g_xyzw[b * NN + ia];
        float4 pb = g_xyzw[b * NN + ib];
        float dot = fmaf(pa.x, pb.x, fmaf(pa.y, pb.y, pa.z * pb.z));
        float d2 = fmaxf(pa.w + pb.w - 2.0f * dot, 1e-12f);
        x28[p][ch] = sqrtf(d2);
    }

    for (int t = tid; t < TP * 64; t += 128) {
        int p = t >> 6, c = t & 63;
        in2[p][c] = feature[(size_t)(b * NN + sp_g[p]) * IN_CH + c];
    }
    __syncthreads();

    const float invs = 1.0f / sqrtf(1.0f + 1e-5f);
    const int c  = tid & 63;
    const int pb = (tid >> 6) * 8;

    // layer 1: 28 -> 64 (7 float4 k-groups)
    {
        float acc[8];
        #pragma unroll
        for (int p = 0; p < 8; p++) acc[p] = b1[c];
        #pragma unroll
        for (int k4 = 0; k4 < 7; k4++) {
            float wa = w1[(4 * k4 + 0) * 64 + c];
            float wb = w1[(4 * k4 + 1) * 64 + c];
            float wc = w1[(4 * k4 + 2) * 64 + c];
            float wd = w1[(4 * k4 + 3) * 64 + c];
            #pragma unroll
            for (int p = 0; p < 8; p++) {
                float4 xv = reinterpret_cast<const float4*>(&x28[pb + p][0])[k4];
                acc[p] = fmaf(xv.x, wa, acc[p]);
                acc[p] = fmaf(xv.y, wb, acc[p]);
                acc[p] = fmaf(xv.z, wc, acc[p]);
                acc[p] = fmaf(xv.w, wd, acc[p]);
            }
        }
        float sc = g1[c] * invs, sh = be1[c];
        #pragma unroll
        for (int p = 0; p < 8; p++) {
            float v = fmaf(acc[p], sc, sh);
            t1s[pb + p][c] = (v >= 0.0f) ? v : 0.2f * v;
        }
    }
    __syncthreads();

    // layer 2: 64 -> 64 (16 float4 k-groups), output into in2[p][64..127]
    {
        float acc[8];
        #pragma unroll
        for (int p = 0; p < 8; p++) acc[p] = b2[c];
        #pragma unroll
        for (int k4 = 0; k4 < 16; k4++) {
            float wa = w2[(4 * k4 + 0) * 64 + c];
            float wb = w2[(4 * k4 + 1) * 64 + c];
            float wc = w2[(4 * k4 + 2) * 64 + c];
            float wd = w2[(4 * k4 + 3) * 64 + c];
            #pragma unroll
            for (int p = 0; p < 8; p++) {
                float4 xv = reinterpret_cast<const float4*>(&t1s[pb + p][0])[k4];
                acc[p] = fmaf(xv.x, wa, acc[p]);
                acc[p] = fmaf(xv.y, wb, acc[p]);
                acc[p] = fmaf(xv.z, wc, acc[p]);
                acc[p] = fmaf(xv.w, wd, acc[p]);
            }
        }
        float sc = g2[c] * invs, sh = be2[c];
        #pragma unroll
        for (int p = 0; p < 8; p++) {
            float v = fmaf(acc[p], sc, sh);
            in2[pb + p][64 + c] = (v >= 0.0f) ? v : 0.2f * v;
        }
    }
    __syncthreads();

    // layer 3: 128 -> 128 (32 float4 k-groups)
    {
        float acc[TP];
        #pragma unroll
        for (int p = 0; p < TP; p++) acc[p] = b3[tid];
        #pragma unroll 4
        for (int k4 = 0; k4 < 32; k4++) {
            float wa = w3[(4 * k4 + 0) * 128 + tid];
            float wb = w3[(4 * k4 + 1) * 128 + tid];
            float wc = w3[(4 * k4 + 2) * 128 + tid];
            float wd = w3[(4 * k4 + 3) * 128 + tid];
            #pragma unroll
            for (int p = 0; p < TP; p++) {
                float4 xv = reinterpret_cast<const float4*>(&in2[p][0])[k4];
                acc[p] = fmaf(xv.x, wa, acc[p]);
                acc[p] = fmaf(xv.y, wb, acc[p]);
                acc[p] = fmaf(xv.z, wc, acc[p]);
                acc[p] = fmaf(xv.w, wd, acc[p]);
            }
        }
        float sc = g3[tid] * invs, sh = be3[tid];
        const size_t obase = (size_t)BB * SS * 3;
        #pragma unroll
        for (int p = 0; p < TP; p++) {
            float v = fmaf(acc[p], sc, sh);
            v = (v >= 0.0f) ? v : 0.2f * v;
            out[obase + (size_t)((b * SS + s0 + p)) * OUT_CH + tid] = v;
        }
    }
}

// ---------------- launch ----------------
extern "C" void kernel_launch(void* const* d_in, const int* in_sizes, int n_in,
                              void* d_out, int out_size) {
    const float* xyz     = (const float*)d_in[0];
    const float* feature = (const float*)d_in[1];
    const int*   sample  = (const int*)d_in[2];
    const float* w1  = (const float*)d_in[3];
    const float* b1  = (const float*)d_in[4];
    const float* g1  = (const float*)d_in[5];
    const float* be1 = (const float*)d_in[6];
    const float* w2  = (const float*)d_in[7];
    const float* b2  = (const float*)d_in[8];
    const float* g2  = (const float*)d_in[9];
    const float* be2 = (const float*)d_in[10];
    const float* w3  = (const float*)d_in[11];
    const float* b3  = (const float*)d_in[12];
    const float* g3  = (const float*)d_in[13];
    const float* be3 = (const float*)d_in[14];
    float* out = (float*)d_out;

    // 64KB dynamic smem for the whole-batch sort (host-side attr, idempotent)
    cudaFuncSetAttribute(k_sort_all, cudaFuncAttributeMaxDynamicSharedMemorySize, NN * 8);

    k_prep_gather<<<(BB * (NN + SS) + 255) / 256, 256>>>(xyz, sample, out);

    k_sort_all<<<BB, 1024, NN * 8>>>(xyz);

    k_scatter_full<<<BB * NN / 256, 256>>>(sample);
    k_scatter_samp<<<BB * NN / 256, 256>>>();

    k_knn<<<dim3(SS / 8, BB, 2), 256>>>();

    k_fused<<<BB * SS / TP, 128>>>(feature, sample,
                                   w1, b1, g1, be1,
                                   w2, b2, g2, be2,
                                   w3, b3, g3, be3,
                                   out);
}

// round 13
// speedup vs baseline: 1.2083x; 1.2083x over previous
#include <cuda_runtime.h>
#include <math_constants.h>

#define BB 2
#define NN 8192
#define SS 4096
#define IN_CH 64
#define TRANS_CH 64
#define OUT_CH 128
#define TP 16         // sampled points per block in fused kernel

typedef unsigned long long u64;

// ---------------- device scratch (no cudaMalloc allowed) ----------------
__device__ float4 g_xyzw[BB * NN];      // x,y,z,|x|^2
__device__ u64    g_keys [BB * NN];     // (flipped z bits << 32) | idx-in-batch
__device__ u64    g_keys2[BB * NN];     // final sorted keys (double buffer)
__device__ int    g_srank[BB * NN];     // sorted pos -> s+1 (0 = not sampled)
__device__ int    g_ccnt[BB * 32];      // members per 256-chunk

// z-sorted full set + compacted sampled subset
__device__ float4 g_pfull[BB * NN];
__device__ float  g_zfull[BB * NN];
__device__ int    g_ofull[BB * NN];     // sorted pos -> original global id
__device__ float4 g_psamp[BB * SS];
__device__ float  g_zsamp[BB * SS];
__device__ int    g_osamp[BB * SS];     // sorted pos -> sample-space pos

// KNN results, keyed by SAMPLE-SPACE position s
__device__ int    g_aidx[BB * SS * 4];
__device__ float  g_adist[BB * SS * 4];
__device__ int    g_saidx[BB * SS * 4];
__device__ float  g_sadist[BB * SS * 4];

// ---------------- helpers ----------------
__device__ __forceinline__ void insert4f(float (&bd)[4], int (&bi)[4], float d, int j) {
    if (d >= bd[3]) return;
    if (d < bd[2]) {
        bd[3] = bd[2]; bi[3] = bi[2];
        if (d < bd[1]) {
            bd[2] = bd[1]; bi[2] = bi[1];
            if (d < bd[0]) {
                bd[1] = bd[0]; bi[1] = bi[0];
                bd[0] = d; bi[0] = j;
            } else { bd[1] = d; bi[1] = j; }
        } else { bd[2] = d; bi[2] = j; }
    } else { bd[3] = d; bi[3] = j; }
}

__device__ __forceinline__ u64 zkey(float z, unsigned idx) {
    unsigned bits = __float_as_uint(z);
    bits = (bits & 0x80000000u) ? ~bits : (bits | 0x80000000u);
    return ((u64)bits << 32) | idx;
}

// compare-exchange primitives (keys are UNIQUE -> min/max == network swap)
__device__ __forceinline__ void cmp_swap_pair(u64& lo, u64& hi, bool up) {
    u64 mn = lo < hi ? lo : hi;
    u64 mx = lo < hi ? hi : lo;
    lo = up ? mn : mx;
    hi = up ? mx : mn;
}
__device__ __forceinline__ u64 shfl_cmp(u64 v, int gi, int j, int k) {
    u64 o = __shfl_xor_sync(0xffffffffu, v, j);
    bool keepmin = (((gi & j) == 0) == ((gi & k) == 0));
    u64 mn = v < o ? v : o, mx = v < o ? o : v;
    return keepmin ? mn : mx;
}
__device__ __forceinline__ void reg_stage2(u64& a, u64& b, int ga, int k) {
    if (k >= 64) cmp_swap_pair(a, b, ((ga & k) == 0));
    int j0 = (k >> 1) > 16 ? 16 : (k >> 1);
    #pragma unroll
    for (int j = 16; j >= 1; j >>= 1) {
        if (j <= j0) {
            a = shfl_cmp(a, ga, j, k);
            b = shfl_cmp(b, ga + 32, j, k);
        }
    }
}

// ---------------- K0: fused prep + sampled_xyz gather ----------------
__global__ void k_prep_gather(const float* __restrict__ xyz,
                              const int*   __restrict__ sample,
                              float* __restrict__ out) {
    int i = blockIdx.x * blockDim.x + threadIdx.x;
    if (i < BB * NN) {
        float x = xyz[3 * i], y = xyz[3 * i + 1], z = xyz[3 * i + 2];
        float sq = fmaf(x, x, fmaf(y, y, z * z));
        g_xyzw[i] = make_float4(x, y, z, sq);
        g_keys[i] = zkey(z, (unsigned)(i % NN));
    } else {
        int j = i - BB * NN;
        if (j >= BB * SS) return;
        int b = j / SS;
        int g = sample[j];
        const float* p = xyz + 3 * (b * NN + g);
        out[3 * j + 0] = p[0];
        out[3 * j + 1] = p[1];
        out[3 * j + 2] = p[2];
    }
}

// ---------------- sort stage A: local 2048-chunks, stages k=2..2048 ----------------
__global__ __launch_bounds__(1024) void k_sort_local() {
    __shared__ u64 sk[2048];
    const int base = blockIdx.x * 2048;
    u64* gk = g_keys + blockIdx.y * NN + base;
    const int t = threadIdx.x, w = t >> 5, l = t & 31;
    const int ia = (w << 6) + l, ib = ia + 32;
    const int ga = base + ia;

    u64 a = gk[ia], b = gk[ib];

    #pragma unroll
    for (int k = 2; k <= 64; k <<= 1)
        reg_stage2(a, b, ga, k);

    #pragma unroll
    for (int k = 128; k <= 2048; k <<= 1) {
        sk[ia] = a; sk[ib] = b;
        __syncthreads();
        for (int j = k >> 1; j >= 64; j >>= 1) {
            #pragma unroll
            for (int i = t; i < 2048; i += 1024) {
                int p = i ^ j;
                if (p > i) {
                    u64 x = sk[i], y = sk[p];
                    bool up = (((base + i) & k) == 0);
                    if ((x > y) == up) { sk[i] = y; sk[p] = x; }
                }
            }
            __syncthreads();
        }
        a = sk[ia]; b = sk[ib];
        reg_stage2(a, b, ga, k);
    }
    gk[ia] = a; gk[ib] = b;
}

// ---------------- sort stage B: 4096-window, stage k=4096 (in-place) ----------------
__global__ __launch_bounds__(1024) void k_fin4k() {
    const int k = 4096;
    __shared__ u64 sk[4096];
    const int base = blockIdx.x * 4096;
    u64* gk = g_keys + blockIdx.y * NN + base;
    const int t = threadIdx.x, w = t >> 5, l = t & 31;

    #pragma unroll
    for (int i = t; i < 4096; i += 1024) sk[i] = gk[i];
    __syncthreads();

    for (int j = 2048; j >= 64; j >>= 1) {
        #pragma unroll
        for (int i = t; i < 4096; i += 1024) {
            int p = i ^ j;
            if (p > i) {
                u64 x = sk[i], y = sk[p];
                bool up = (((base + i) & k) == 0);
                if ((x > y) == up) { sk[i] = y; sk[p] = x; }
            }
        }
        __syncthreads();
    }

    const int g0 = base + (w << 7) + l;
    u64 r0 = sk[(w << 7) + l];
    u64 r1 = sk[(w << 7) + l + 32];
    u64 r2 = sk[(w << 7) + l + 64];
    u64 r3 = sk[(w << 7) + l + 96];
    cmp_swap_pair(r0, r1, ((g0 & k) == 0));
    cmp_swap_pair(r2, r3, (((g0 + 64) & k) == 0));
    #pragma unroll
    for (int j = 16; j >= 1; j >>= 1) {
        r0 = shfl_cmp(r0, g0,      j, k);
        r1 = shfl_cmp(r1, g0 + 32, j, k);
        r2 = shfl_cmp(r2, g0 + 64, j, k);
        r3 = shfl_cmp(r3, g0 + 96, j, k);
    }
    gk[(w << 7) + l]      = r0;
    gk[(w << 7) + l + 32] = r1;
    gk[(w << 7) + l + 64] = r2;
    gk[(w << 7) + l + 96] = r3;
}

// ---------------- sort stage C: full k=8192 stage, g_keys -> g_keys2 ----------------
__global__ __launch_bounds__(1024) void k_fin8k() {
    const int k = 8192;
    __shared__ u64 sk[4096];
    const int base = blockIdx.x * 4096;          // window 0 or 1 (batch-local)
    const u64* gin  = g_keys  + blockIdx.y * NN;
    u64*       gout = g_keys2 + blockIdx.y * NN + base;
    const int t = threadIdx.x, w = t >> 5, l = t & 31;

    // j = 4096 pass: window 0 keeps min, window 1 keeps max
    #pragma unroll
    for (int i = t; i < 4096; i += 1024) {
        u64 a = gin[base + i];
        u64 b = gin[(base + i) ^ 4096];
        u64 mn = a < b ? a : b, mx = a < b ? b : a;
        sk[i] = (base == 0) ? mn : mx;
    }
    __syncthreads();

    for (int j = 2048; j >= 64; j >>= 1) {
        #pragma unroll
        for (int i = t; i < 4096; i += 1024) {
            int p = i ^ j;
            if (p > i) {
                u64 x = sk[i], y = sk[p];
                if (x > y) { sk[i] = y; sk[p] = x; }   // up = true everywhere
            }
        }
        __syncthreads();
    }

    const int g0 = base + (w << 7) + l;
    u64 r0 = sk[(w << 7) + l];
    u64 r1 = sk[(w << 7) + l + 32];
    u64 r2 = sk[(w << 7) + l + 64];
    u64 r3 = sk[(w << 7) + l + 96];
    cmp_swap_pair(r0, r1, true);
    cmp_swap_pair(r2, r3, true);
    #pragma unroll
    for (int j = 16; j >= 1; j >>= 1) {
        r0 = shfl_cmp(r0, g0,      j, k);
        r1 = shfl_cmp(r1, g0 + 32, j, k);
        r2 = shfl_cmp(r2, g0 + 64, j, k);
        r3 = shfl_cmp(r3, g0 + 96, j, k);
    }
    gout[(w << 7) + l]      = r0;
    gout[(w << 7) + l + 32] = r1;
    gout[(w << 7) + l + 64] = r2;
    gout[(w << 7) + l + 96] = r3;
}

// ---------------- compaction pass 1: full scatter + membership + chunk counts ----------------
__global__ __launch_bounds__(256) void k_scatter_full(const int* __restrict__ sample) {
    const int i = blockIdx.x * 256 + threadIdx.x;   // index in [0, BB*NN)
    const int b = i / NN;
    const int lane = threadIdx.x & 31, wid = threadIdx.x >> 5;

    u64 key = g_keys2[i];
    int g = (int)(key & 0xffffffffu);
    float4 v = g_xyzw[b * NN + g];
    g_pfull[i] = v;
    g_zfull[i] = v.z;
    g_ofull[i] = g;

    // membership: binary search in sorted sample[b]
    const int* sm = sample + b * SS;
    int lo = 0, hi = SS;
    while (lo < hi) { int mid = (lo + hi) >> 1; if (sm[mid] < g) lo = mid + 1; else hi = mid; }
    int s = (lo < SS && sm[lo] == g) ? (lo + 1) : 0;
    g_srank[i] = s;

    unsigned bal = __ballot_sync(0xffffffffu, s > 0);
    __shared__ int ws[8];
    if (lane == 0) ws[wid] = __popc(bal);
    __syncthreads();
    if (threadIdx.x == 0) {
        int tot = 0;
        #pragma unroll
        for (int w = 0; w < 8; w++) tot += ws[w];
        g_ccnt[blockIdx.x] = tot;
    }
}

// ---------------- compaction pass 2: rank + scatter sampled subset ----------------
__global__ __launch_bounds__(256) void k_scatter_samp() {
    const int i = blockIdx.x * 256 + threadIdx.x;
    const int b = i / NN;
    const int c = blockIdx.x & 31;                  // chunk within batch (32 per batch)
    const int lane = threadIdx.x & 31, wid = threadIdx.x >> 5;

    int s = g_srank[i];
    bool m = (s > 0);

    unsigned bal = __ballot_sync(0xffffffffu, m);
    int lrank = __popc(bal & ((1u << lane) - 1u));
    __shared__ int ws[8];
    __shared__ int coff;
    if (lane == 0) ws[wid] = __popc(bal);
    if (wid == 0) {                                 // prefix over preceding chunks
        int v = (lane < c) ? g_ccnt[b * 32 + lane] : 0;
        #pragma unroll
        for (int off = 16; off; off >>= 1) v += __shfl_xor_sync(0xffffffffu, v, off);
        if (lane == 0) coff = v;
    }
    __syncthreads();
    int woff = 0;
    #pragma unroll
    for (int w = 0; w < 8; w++) if (w < wid) woff += ws[w];

    if (m) {
        u64 key = g_keys2[i];
        int g = (int)(key & 0xffffffffu);
        int pos = coff + woff + lrank;
        float4 v = g_xyzw[b * NN + g];
        g_psamp[b * SS + pos] = v;
        g_zsamp[b * SS + pos] = v.z;
        g_osamp[b * SS + pos] = s - 1;
    }
}

// ---------------- KNN: pruned two-sided scan, 64-wide, lazy lane-local threshold ----------------
// (round-9 proven version; in-loop full merges measured 56us SLOWER in round 10)
__global__ __launch_bounds__(256) void k_knn() {
    const bool FULLV = (blockIdx.z == 0);
    const int b    = blockIdx.y;
    const int warp = threadIdx.x >> 5;
    const int lane = threadIdx.x & 31;
    const int r    = blockIdx.x * 8 + warp;      // rank in z-sorted sampled array

    const int M = FULLV ? NN : SS;
    const float4* pts = FULLV ? (g_pfull + b * NN) : (g_psamp + b * SS);
    const float*  zz  = FULLV ? (g_zfull + b * NN) : (g_zsamp + b * SS);
    const float4  qp  = g_psamp[b * SS + r];

    int start;
    if (FULLV) {
        int lo = 0, hi = NN;
        while (lo < hi) { int mid = (lo + hi) >> 1; if (zz[mid] < qp.z) lo = mid + 1; else hi = mid; }
        start = lo;
    } else {
        start = r;
    }

    float bd[4] = {CUDART_INF_F, CUDART_INF_F, CUDART_INF_F, CUDART_INF_F};
    int   bi[4] = {0, 0, 0, 0};
    float thr = CUDART_INF_F;

    int ptrL = start, ptrR = start;
    while (true) {
        bool canL = ptrL > 0, canR = ptrR < M;
        if (!canL && !canR) break;
        float dzL = canL ? (qp.z - zz[ptrL - 1]) : CUDART_INF_F;
        float dzR = canR ? (zz[ptrR] - qp.z)     : CUDART_INF_F;
        float mdz = fminf(dzL, dzR);
        if (mdz * mdz > thr) break;
        int i0, i1;
        if (dzR <= dzL) { i0 = ptrR + lane; i1 = i0 + 32; ptrR += 64; }
        else            { i0 = ptrL - 64 + lane; i1 = i0 + 32; ptrL -= 64; }
        bool changed = false;
        if (i0 >= 0 && i0 < M) {
            float4 c = pts[i0];
            float dot = fmaf(qp.x, c.x, fmaf(qp.y, c.y, qp.z * c.z));
            float d2  = fmaxf(qp.w + c.w - 2.0f * dot, 1e-12f);
            changed |= (d2 < bd[3]);
            insert4f(bd, bi, d2, i0);
        }
        if (i1 >= 0 && i1 < M) {
            float4 c = pts[i1];
            float dot = fmaf(qp.x, c.x, fmaf(qp.y, c.y, qp.z * c.z));
            float d2  = fmaxf(qp.w + c.w - 2.0f * dot, 1e-12f);
            changed |= (d2 < bd[3]);
            insert4f(bd, bi, d2, i1);
        }
        if (__any_sync(0xffffffffu, changed)) {
            float tt = bd[3];
            #pragma unroll
            for (int off = 16; off; off >>= 1)
                tt = fminf(tt, __shfl_xor_sync(0xffffffffu, tt, off));
            thr = tt;
        }
    }

    #pragma unroll
    for (int off = 16; off; off >>= 1) {
        float od[4]; int oi[4];
        #pragma unroll
        for (int k = 0; k < 4; k++) {
            od[k] = __shfl_xor_sync(0xffffffffu, bd[k], off);
            oi[k] = __shfl_xor_sync(0xffffffffu, bi[k], off);
        }
        #pragma unroll
        for (int k = 0; k < 4; k++) insert4f(bd, bi, od[k], oi[k]);
    }

    if (lane == 0) {
        int s = g_osamp[b * SS + r];
        if (FULLV) {
            #pragma unroll
            for (int k = 0; k < 4; k++) {
                g_aidx [(b * SS + s) * 4 + k] = g_ofull[b * NN + bi[k]];
                g_adist[(b * SS + s) * 4 + k] = sqrtf(bd[k]);
            }
        } else {
            #pragma unroll
            for (int k = 0; k < 4; k++) {
                g_saidx [(b * SS + s) * 4 + k] = g_osamp[b * SS + bi[k]];
                g_sadist[(b * SS + s) * 4 + k] = sqrtf(bd[k]);
            }
        }
    }
}

// ---------------- fused 28-feature build + 3-layer MLP (TP=16, float4 smem reads) ----------------
__global__ __launch_bounds__(128) void k_fused(
    const float* __restrict__ feature,
    const int*   __restrict__ sample,
    const float* __restrict__ w1, const float* __restrict__ b1,
    const float* __restrict__ g1, const float* __restrict__ be1,
    const float* __restrict__ w2, const float* __restrict__ b2,
    const float* __restrict__ g2, const float* __restrict__ be2,
    const float* __restrict__ w3, const float* __restrict__ b3,
    const float* __restrict__ g3, const float* __restrict__ be3,
    float* __restrict__ out)
{
    __shared__ float x28[TP][28];
    __shared__ float t1s[TP][64];
    __shared__ float in2[TP][128];
    __shared__ int sp_g[TP];
    __shared__ int sp_a[TP][4];
    __shared__ int sp_ga[TP][4];

    const int tid = threadIdx.x;
    const int blk = blockIdx.x;
    const int b   = blk / (SS / TP);
    const int s0  = (blk % (SS / TP)) * TP;

    if (tid < TP) {
        int p = tid;
        int s = s0 + p;
        int g = sample[b * SS + s];
        sp_g[p] = g;
        #pragma unroll
        for (int k = 0; k < 4; k++) {
            sp_a[p][k] = g_aidx[(b * SS + s) * 4 + k];
            int sa = g_saidx[(b * SS + s) * 4 + k];
            sp_ga[p][k] = sample[b * SS + sa];
        }
        #pragma unroll
        for (int k = 0; k < 3; k++) {
            x28[p][k]     = g_adist[(b * SS + s) * 4 + 1 + k];
            x28[p][6 + k] = g_sadist[(b * SS + s) * 4 + 1 + k];
        }
    }
    __syncthreads();

    for (int t = tid; t < TP * 22; t += 128) {
        int p = t / 22, w = t % 22;
        int ia, ib, ch;
        if (w < 3) {
            int pi = (w < 2) ? 1 : 2;
            int pj = (w == 0) ? 2 : 3;
            ia = sp_a[p][pi]; ib = sp_a[p][pj]; ch = 3 + w;
        } else if (w < 6) {
            int u = w - 3;
            int pi = (u < 2) ? 1 : 2;
            int pj = (u == 0) ? 2 : 3;
            ia = sp_ga[p][pi]; ib = sp_ga[p][pj]; ch = 9 + u;
        } else {
            int u = w - 6;
            int i = u >> 2, j = u & 3;
            ia = sp_a[p][i]; ib = sp_ga[p][j]; ch = 12 + u;
        }
        float4 pa = g_xyzw[b * NN + ia];
        float4 pb = g_xyzw[b * NN + ib];
        float dot = fmaf(pa.x, pb.x, fmaf(pa.y, pb.y, pa.z * pb.z));
        float d2 = fmaxf(pa.w + pb.w - 2.0f * dot, 1e-12f);
        x28[p][ch] = sqrtf(d2);
    }

    for (int t = tid; t < TP * 64; t += 128) {
        int p = t >> 6, c = t & 63;
        in2[p][c] = feature[(size_t)(b * NN + sp_g[p]) * IN_CH + c];
    }
    __syncthreads();

    const float invs = 1.0f / sqrtf(1.0f + 1e-5f);
    const int c  = tid & 63;
    const int pb = (tid >> 6) * 8;

    // layer 1: 28 -> 64 (7 float4 k-groups)
    {
        float acc[8];
        #pragma unroll
        for (int p = 0; p < 8; p++) acc[p] = b1[c];
        #pragma unroll
        for (int k4 = 0; k4 < 7; k4++) {
            float wa = w1[(4 * k4 + 0) * 64 + c];
            float wb = w1[(4 * k4 + 1) * 64 + c];
            float wc = w1[(4 * k4 + 2) * 64 + c];
            float wd = w1[(4 * k4 + 3) * 64 + c];
            #pragma unroll
            for (int p = 0; p < 8; p++) {
                float4 xv = reinterpret_cast<const float4*>(&x28[pb + p][0])[k4];
                acc[p] = fmaf(xv.x, wa, acc[p]);
                acc[p] = fmaf(xv.y, wb, acc[p]);
                acc[p] = fmaf(xv.z, wc, acc[p]);
                acc[p] = fmaf(xv.w, wd, acc[p]);
            }
        }
        float sc = g1[c] * invs, sh = be1[c];
        #pragma unroll
        for (int p = 0; p < 8; p++) {
            float v = fmaf(acc[p], sc, sh);
            t1s[pb + p][c] = (v >= 0.0f) ? v : 0.2f * v;
        }
    }
    __syncthreads();

    // layer 2: 64 -> 64 (16 float4 k-groups), output into in2[p][64..127]
    {
        float acc[8];
        #pragma unroll
        for (int p = 0; p < 8; p++) acc[p] = b2[c];
        #pragma unroll
        for (int k4 = 0; k4 < 16; k4++) {
            float wa = w2[(4 * k4 + 0) * 64 + c];
            float wb = w2[(4 * k4 + 1) * 64 + c];
            float wc = w2[(4 * k4 + 2) * 64 + c];
            float wd = w2[(4 * k4 + 3) * 64 + c];
            #pragma unroll
            for (int p = 0; p < 8; p++) {
                float4 xv = reinterpret_cast<const float4*>(&t1s[pb + p][0])[k4];
                acc[p] = fmaf(xv.x, wa, acc[p]);
                acc[p] = fmaf(xv.y, wb, acc[p]);
                acc[p] = fmaf(xv.z, wc, acc[p]);
                acc[p] = fmaf(xv.w, wd, acc[p]);
            }
        }
        float sc = g2[c] * invs, sh = be2[c];
        #pragma unroll
        for (int p = 0; p < 8; p++) {
            float v = fmaf(acc[p], sc, sh);
            in2[pb + p][64 + c] = (v >= 0.0f) ? v : 0.2f * v;
        }
    }
    __syncthreads();

    // layer 3: 128 -> 128 (32 float4 k-groups)
    {
        float acc[TP];
        #pragma unroll
        for (int p = 0; p < TP; p++) acc[p] = b3[tid];
        #pragma unroll 4
        for (int k4 = 0; k4 < 32; k4++) {
            float wa = w3[(4 * k4 + 0) * 128 + tid];
            float wb = w3[(4 * k4 + 1) * 128 + tid];
            float wc = w3[(4 * k4 + 2) * 128 + tid];
            float wd = w3[(4 * k4 + 3) * 128 + tid];
            #pragma unroll
            for (int p = 0; p < TP; p++) {
                float4 xv = reinterpret_cast<const float4*>(&in2[p][0])[k4];
                acc[p] = fmaf(xv.x, wa, acc[p]);
                acc[p] = fmaf(xv.y, wb, acc[p]);
                acc[p] = fmaf(xv.z, wc, acc[p]);
                acc[p] = fmaf(xv.w, wd, acc[p]);
            }
        }
        float sc = g3[tid] * invs, sh = be3[tid];
        const size_t obase = (size_t)BB * SS * 3;
        #pragma unroll
        for (int p = 0; p < TP; p++) {
            float v = fmaf(acc[p], sc, sh);
            v = (v >= 0.0f) ? v : 0.2f * v;
            out[obase + (size_t)((b * SS + s0 + p)) * OUT_CH + tid] = v;
        }
    }
}

// ---------------- launch ----------------
extern "C" void kernel_launch(void* const* d_in, const int* in_sizes, int n_in,
                              void* d_out, int out_size) {
    const float* xyz     = (const float*)d_in[0];
    const float* feature = (const float*)d_in[1];
    const int*   sample  = (const int*)d_in[2];
    const float* w1  = (const float*)d_in[3];
    const float* b1  = (const float*)d_in[4];
    const float* g1  = (const float*)d_in[5];
    const float* be1 = (const float*)d_in[6];
    const float* w2  = (const float*)d_in[7];
    const float* b2  = (const float*)d_in[8];
    const float* g2  = (const float*)d_in[9];
    const float* be2 = (const float*)d_in[10];
    const float* w3  = (const float*)d_in[11];
    const float* b3  = (const float*)d_in[12];
    const float* g3  = (const float*)d_in[13];
    const float* be3 = (const float*)d_in[14];
    float* out = (float*)d_out;

    k_prep_gather<<<(BB * (NN + SS) + 255) / 256, 256>>>(xyz, sample, out);

    k_sort_local<<<dim3(NN / 2048, BB), 1024>>>();   // k = 2..2048
    k_fin4k     <<<dim3(NN / 4096, BB), 1024>>>();   // k = 4096
    k_fin8k     <<<dim3(NN / 4096, BB), 1024>>>();   // k = 8192 (full stage, -> g_keys2)

    k_scatter_full<<<BB * NN / 256, 256>>>(sample);
    k_scatter_samp<<<BB * NN / 256, 256>>>();

    k_knn<<<dim3(SS / 8, BB, 2), 256>>>();

    k_fused<<<BB * SS / TP, 128>>>(feature, sample,
                                   w1, b1, g1, be1,
                                   w2, b2, g2, be2,
                                   w3, b3, g3, be3,
                                   out);
}

// round 14
// speedup vs baseline: 1.2632x; 1.0454x over previous
#include <cuda_runtime.h>
#include <math_constants.h>

#define BB 2
#define NN 8192
#define SS 4096
#define IN_CH 64
#define TRANS_CH 64
#define OUT_CH 128
#define TP 16         // sampled points per block in fused kernel

typedef unsigned long long u64;

// ---------------- device scratch (no cudaMalloc allowed) ----------------
__device__ float4 g_xyzw[BB * NN];      // x,y,z,|x|^2
__device__ u64    g_keys [BB * NN];     // (flipped z bits << 32) | idx-in-batch
__device__ u64    g_keys2[BB * NN];     // final sorted keys (double buffer)
__device__ int    g_srank[BB * NN];     // sorted pos -> s+1 (0 = not sampled)
__device__ int    g_ccnt[BB * 32];      // members per 256-chunk

// z-sorted full set + compacted sampled subset
__device__ float4 g_pfull[BB * NN];
__device__ float  g_zfull[BB * NN];
__device__ int    g_ofull[BB * NN];     // sorted pos -> original global id
__device__ float4 g_psamp[BB * SS];
__device__ float  g_zsamp[BB * SS];
__device__ int    g_osamp[BB * SS];     // sorted pos -> sample-space pos

// KNN results, keyed by SAMPLE-SPACE position s
__device__ int    g_aidx[BB * SS * 4];
__device__ float  g_adist[BB * SS * 4];
__device__ int    g_saidx[BB * SS * 4];
__device__ float  g_sadist[BB * SS * 4];

// ---------------- helpers ----------------
__device__ __forceinline__ void insert4f(float (&bd)[4], int (&bi)[4], float d, int j) {
    if (d >= bd[3]) return;
    if (d < bd[2]) {
        bd[3] = bd[2]; bi[3] = bi[2];
        if (d < bd[1]) {
            bd[2] = bd[1]; bi[2] = bi[1];
            if (d < bd[0]) {
                bd[1] = bd[0]; bi[1] = bi[0];
                bd[0] = d; bi[0] = j;
            } else { bd[1] = d; bi[1] = j; }
        } else { bd[2] = d; bi[2] = j; }
    } else { bd[3] = d; bi[3] = j; }
}

__device__ __forceinline__ u64 zkey(float z, unsigned idx) {
    unsigned bits = __float_as_uint(z);
    bits = (bits & 0x80000000u) ? ~bits : (bits | 0x80000000u);
    return ((u64)bits << 32) | idx;
}

// compare-exchange primitives (keys are UNIQUE -> min/max == network swap)
__device__ __forceinline__ void cmp_swap_pair(u64& lo, u64& hi, bool up) {
    u64 mn = lo < hi ? lo : hi;
    u64 mx = lo < hi ? hi : lo;
    lo = up ? mn : mx;
    hi = up ? mx : mn;
}
__device__ __forceinline__ u64 shfl_cmp(u64 v, int gi, int j, int k) {
    u64 o = __shfl_xor_sync(0xffffffffu, v, j);
    bool keepmin = (((gi & j) == 0) == ((gi & k) == 0));
    u64 mn = v < o ? v : o, mx = v < o ? o : v;
    return keepmin ? mn : mx;
}
__device__ __forceinline__ void reg_stage2(u64& a, u64& b, int ga, int k) {
    if (k >= 64) cmp_swap_pair(a, b, ((ga & k) == 0));
    int j0 = (k >> 1) > 16 ? 16 : (k >> 1);
    #pragma unroll
    for (int j = 16; j >= 1; j >>= 1) {
        if (j <= j0) {
            a = shfl_cmp(a, ga, j, k);
            b = shfl_cmp(b, ga + 32, j, k);
        }
    }
}

// warp butterfly merge of per-lane sorted top4 lists (entries disjoint across lanes)
__device__ __forceinline__ void warp_merge4(float (&bd)[4], int (&bi)[4]) {
    #pragma unroll
    for (int off = 16; off; off >>= 1) {
        float od[4]; int oi[4];
        #pragma unroll
        for (int k = 0; k < 4; k++) {
            od[k] = __shfl_xor_sync(0xffffffffu, bd[k], off);
            oi[k] = __shfl_xor_sync(0xffffffffu, bi[k], off);
        }
        #pragma unroll
        for (int k = 0; k < 4; k++) insert4f(bd, bi, od[k], oi[k]);
    }
}

// ---------------- K0: fused prep + sampled_xyz gather ----------------
__global__ void k_prep_gather(const float* __restrict__ xyz,
                              const int*   __restrict__ sample,
                              float* __restrict__ out) {
    int i = blockIdx.x * blockDim.x + threadIdx.x;
    if (i < BB * NN) {
        float x = xyz[3 * i], y = xyz[3 * i + 1], z = xyz[3 * i + 2];
        float sq = fmaf(x, x, fmaf(y, y, z * z));
        g_xyzw[i] = make_float4(x, y, z, sq);
        g_keys[i] = zkey(z, (unsigned)(i % NN));
    } else {
        int j = i - BB * NN;
        if (j >= BB * SS) return;
        int b = j / SS;
        int g = sample[j];
        const float* p = xyz + 3 * (b * NN + g);
        out[3 * j + 0] = p[0];
        out[3 * j + 1] = p[1];
        out[3 * j + 2] = p[2];
    }
}

// ---------------- sort stage A: local 2048-chunks, stages k=2..2048 ----------------
__global__ __launch_bounds__(1024) void k_sort_local() {
    __shared__ u64 sk[2048];
    const int base = blockIdx.x * 2048;
    u64* gk = g_keys + blockIdx.y * NN + base;
    const int t = threadIdx.x, w = t >> 5, l = t & 31;
    const int ia = (w << 6) + l, ib = ia + 32;
    const int ga = base + ia;

    u64 a = gk[ia], b = gk[ib];

    #pragma unroll
    for (int k = 2; k <= 64; k <<= 1)
        reg_stage2(a, b, ga, k);

    #pragma unroll
    for (int k = 128; k <= 2048; k <<= 1) {
        sk[ia] = a; sk[ib] = b;
        __syncthreads();
        for (int j = k >> 1; j >= 64; j >>= 1) {
            #pragma unroll
            for (int i = t; i < 2048; i += 1024) {
                int p = i ^ j;
                if (p > i) {
                    u64 x = sk[i], y = sk[p];
                    bool up = (((base + i) & k) == 0);
                    if ((x > y) == up) { sk[i] = y; sk[p] = x; }
                }
            }
            __syncthreads();
        }
        a = sk[ia]; b = sk[ib];
        reg_stage2(a, b, ga, k);
    }
    gk[ia] = a; gk[ib] = b;
}

// ---------------- sort stage B: 4096-window, stage k=4096 (in-place) ----------------
__global__ __launch_bounds__(1024) void k_fin4k() {
    const int k = 4096;
    __shared__ u64 sk[4096];
    const int base = blockIdx.x * 4096;
    u64* gk = g_keys + blockIdx.y * NN + base;
    const int t = threadIdx.x, w = t >> 5, l = t & 31;

    #pragma unroll
    for (int i = t; i < 4096; i += 1024) sk[i] = gk[i];
    __syncthreads();

    for (int j = 2048; j >= 64; j >>= 1) {
        #pragma unroll
        for (int i = t; i < 4096; i += 1024) {
            int p = i ^ j;
            if (p > i) {
                u64 x = sk[i], y = sk[p];
                bool up = (((base + i) & k) == 0);
                if ((x > y) == up) { sk[i] = y; sk[p] = x; }
            }
        }
        __syncthreads();
    }

    const int g0 = base + (w << 7) + l;
    u64 r0 = sk[(w << 7) + l];
    u64 r1 = sk[(w << 7) + l + 32];
    u64 r2 = sk[(w << 7) + l + 64];
    u64 r3 = sk[(w << 7) + l + 96];
    cmp_swap_pair(r0, r1, ((g0 & k) == 0));
    cmp_swap_pair(r2, r3, (((g0 + 64) & k) == 0));
    #pragma unroll
    for (int j = 16; j >= 1; j >>= 1) {
        r0 = shfl_cmp(r0, g0,      j, k);
        r1 = shfl_cmp(r1, g0 + 32, j, k);
        r2 = shfl_cmp(r2, g0 + 64, j, k);
        r3 = shfl_cmp(r3, g0 + 96, j, k);
    }
    gk[(w << 7) + l]      = r0;
    gk[(w << 7) + l + 32] = r1;
    gk[(w << 7) + l + 64] = r2;
    gk[(w << 7) + l + 96] = r3;
}

// ---------------- sort stage C: full k=8192 stage, g_keys -> g_keys2 ----------------
__global__ __launch_bounds__(1024) void k_fin8k() {
    const int k = 8192;
    __shared__ u64 sk[4096];
    const int base = blockIdx.x * 4096;          // window 0 or 1 (batch-local)
    const u64* gin  = g_keys  + blockIdx.y * NN;
    u64*       gout = g_keys2 + blockIdx.y * NN + base;
    const int t = threadIdx.x, w = t >> 5, l = t & 31;

    // j = 4096 pass: window 0 keeps min, window 1 keeps max
    #pragma unroll
    for (int i = t; i < 4096; i += 1024) {
        u64 a = gin[base + i];
        u64 b = gin[(base + i) ^ 4096];
        u64 mn = a < b ? a : b, mx = a < b ? b : a;
        sk[i] = (base == 0) ? mn : mx;
    }
    __syncthreads();

    for (int j = 2048; j >= 64; j >>= 1) {
        #pragma unroll
        for (int i = t; i < 4096; i += 1024) {
            int p = i ^ j;
            if (p > i) {
                u64 x = sk[i], y = sk[p];
                if (x > y) { sk[i] = y; sk[p] = x; }   // up = true everywhere
            }
        }
        __syncthreads();
    }

    const int g0 = base + (w << 7) + l;
    u64 r0 = sk[(w << 7) + l];
    u64 r1 = sk[(w << 7) + l + 32];
    u64 r2 = sk[(w << 7) + l + 64];
    u64 r3 = sk[(w << 7) + l + 96];
    cmp_swap_pair(r0, r1, true);
    cmp_swap_pair(r2, r3, true);
    #pragma unroll
    for (int j = 16; j >= 1; j >>= 1) {
        r0 = shfl_cmp(r0, g0,      j, k);
        r1 = shfl_cmp(r1, g0 + 32, j, k);
        r2 = shfl_cmp(r2, g0 + 64, j, k);
        r3 = shfl_cmp(r3, g0 + 96, j, k);
    }
    gout[(w << 7) + l]      = r0;
    gout[(w << 7) + l + 32] = r1;
    gout[(w << 7) + l + 64] = r2;
    gout[(w << 7) + l + 96] = r3;
}

// ---------------- compaction pass 1: full scatter + membership + chunk counts ----------------
__global__ __launch_bounds__(256) void k_scatter_full(const int* __restrict__ sample) {
    const int i = blockIdx.x * 256 + threadIdx.x;   // index in [0, BB*NN)
    const int b = i / NN;
    const int lane = threadIdx.x & 31, wid = threadIdx.x >> 5;

    u64 key = g_keys2[i];
    int g = (int)(key & 0xffffffffu);
    float4 v = g_xyzw[b * NN + g];
    g_pfull[i] = v;
    g_zfull[i] = v.z;
    g_ofull[i] = g;

    // membership: binary search in sorted sample[b]
    const int* sm = sample + b * SS;
    int lo = 0, hi = SS;
    while (lo < hi) { int mid = (lo + hi) >> 1; if (sm[mid] < g) lo = mid + 1; else hi = mid; }
    int s = (lo < SS && sm[lo] == g) ? (lo + 1) : 0;
    g_srank[i] = s;

    unsigned bal = __ballot_sync(0xffffffffu, s > 0);
    __shared__ int ws[8];
    if (lane == 0) ws[wid] = __popc(bal);
    __syncthreads();
    if (threadIdx.x == 0) {
        int tot = 0;
        #pragma unroll
        for (int w = 0; w < 8; w++) tot += ws[w];
        g_ccnt[blockIdx.x] = tot;
    }
}

// ---------------- compaction pass 2: rank + scatter sampled subset ----------------
__global__ __launch_bounds__(256) void k_scatter_samp() {
    const int i = blockIdx.x * 256 + threadIdx.x;
    const int b = i / NN;
    const int c = blockIdx.x & 31;                  // chunk within batch (32 per batch)
    const int lane = threadIdx.x & 31, wid = threadIdx.x >> 5;

    int s = g_srank[i];
    bool m = (s > 0);

    unsigned bal = __ballot_sync(0xffffffffu, m);
    int lrank = __popc(bal & ((1u << lane) - 1u));
    __shared__ int ws[8];
    __shared__ int coff;
    if (lane == 0) ws[wid] = __popc(bal);
    if (wid == 0) {                                 // prefix over preceding chunks
        int v = (lane < c) ? g_ccnt[b * 32 + lane] : 0;
        #pragma unroll
        for (int off = 16; off; off >>= 1) v += __shfl_xor_sync(0xffffffffu, v, off);
        if (lane == 0) coff = v;
    }
    __syncthreads();
    int woff = 0;
    #pragma unroll
    for (int w = 0; w < 8; w++) if (w < wid) woff += ws[w];

    if (m) {
        u64 key = g_keys2[i];
        int g = (int)(key & 0xffffffffu);
        int pos = coff + woff + lrank;
        float4 v = g_xyzw[b * NN + g];
        g_psamp[b * SS + pos] = v;
        g_zsamp[b * SS + pos] = v.z;
        g_osamp[b * SS + pos] = s - 1;
    }
}

// ---------------- KNN: two-phase window scan ----------------
// Phase 1: fixed 256-candidate band around start -> full merge -> TIGHT thr.
// Phase 2: extend outward in 64-blocks; one warp-uniform z check per block.
// (replaces the adaptive serial loop; candidate coverage is a superset of all
//  points with d2 <= thr >= true d4^2 -> exact top-4)
__global__ __launch_bounds__(256) void k_knn() {
    const bool FULLV = (blockIdx.z == 0);
    const int b    = blockIdx.y;
    const int warp = threadIdx.x >> 5;
    const int lane = threadIdx.x & 31;
    const int r    = blockIdx.x * 8 + warp;      // rank in z-sorted sampled array

    const int M = FULLV ? NN : SS;
    const float4* pts = FULLV ? (g_pfull + b * NN) : (g_psamp + b * SS);
    const float*  zz  = FULLV ? (g_zfull + b * NN) : (g_zsamp + b * SS);
    const float4  qp  = g_psamp[b * SS + r];
    const float   qz  = qp.z;

    int start;
    if (FULLV) {
        int lo = 0, hi = NN;
        while (lo < hi) { int mid = (lo + hi) >> 1; if (zz[mid] < qz) lo = mid + 1; else hi = mid; }
        start = lo;
    } else {
        start = r;
    }

    float bd[4] = {CUDART_INF_F, CUDART_INF_F, CUDART_INF_F, CUDART_INF_F};
    int   bi[4] = {0, 0, 0, 0};

    // ---- phase 1: 256 candidates [start-128, start+128), 8 per lane ----
    const int p0 = start - 128;
    #pragma unroll
    for (int u = 0; u < 8; u++) {
        int idx = p0 + (u << 5) + lane;
        if (idx >= 0 && idx < M) {
            float4 c = pts[idx];
            float dot = fmaf(qp.x, c.x, fmaf(qp.y, c.y, qp.z * c.z));
            float d2  = fmaxf(qp.w + c.w - 2.0f * dot, 1e-12f);
            insert4f(bd, bi, d2, idx);
        }
    }
    warp_merge4(bd, bi);              // all lanes now hold exact top4 of the 256
    const float thr = bd[3];          // tight conservative radius^2

    // lanes != 0 restart with empty lists so the FINAL merge stays duplicate-free
    if (lane != 0) {
        #pragma unroll
        for (int k = 0; k < 4; k++) { bd[k] = CUDART_INF_F; bi[k] = 0; }
    }

    // ---- phase 2 right: blocks [base, base+64), z ascending ----
    for (int base = start + 128; base < M; base += 64) {
        float dz = zz[base] - qz;     // min gap in this and all further blocks
        if (dz * dz > thr) break;
        #pragma unroll
        for (int u = 0; u < 2; u++) {
            int idx = base + (u << 5) + lane;
            if (idx < M) {
                float4 c = pts[idx];
                float dot = fmaf(qp.x, c.x, fmaf(qp.y, c.y, qp.z * c.z));
                float d2  = fmaxf(qp.w + c.w - 2.0f * dot, 1e-12f);
                insert4f(bd, bi, d2, idx);
            }
        }
    }

    // ---- phase 2 left: blocks [base, base+64), z descending ----
    for (int base = start - 192; base + 64 > 0; base -= 64) {
        float dz = qz - zz[base + 63];  // min gap in this and all further blocks
        if (dz * dz > thr) break;
        #pragma unroll
        for (int u = 0; u < 2; u++) {
            int idx = base + (u << 5) + lane;
            if (idx >= 0) {
                float4 c = pts[idx];
                float dot = fmaf(qp.x, c.x, fmaf(qp.y, c.y, qp.z * c.z));
                float d2  = fmaxf(qp.w + c.w - 2.0f * dot, 1e-12f);
                insert4f(bd, bi, d2, idx);
            }
        }
    }

    warp_merge4(bd, bi);

    if (lane == 0) {
        int s = g_osamp[b * SS + r];
        if (FULLV) {
            #pragma unroll
            for (int k = 0; k < 4; k++) {
                g_aidx [(b * SS + s) * 4 + k] = g_ofull[b * NN + bi[k]];
                g_adist[(b * SS + s) * 4 + k] = sqrtf(bd[k]);
            }
        } else {
            #pragma unroll
            for (int k = 0; k < 4; k++) {
                g_saidx [(b * SS + s) * 4 + k] = g_osamp[b * SS + bi[k]];
                g_sadist[(b * SS + s) * 4 + k] = sqrtf(bd[k]);
            }
        }
    }
}

// ---------------- fused 28-feature build + 3-layer MLP (TP=16, float4 smem reads) ----------------
__global__ __launch_bounds__(128) void k_fused(
    const float* __restrict__ feature,
    const int*   __restrict__ sample,
    const float* __restrict__ w1, const float* __restrict__ b1,
    const float* __restrict__ g1, const float* __restrict__ be1,
    const float* __restrict__ w2, const float* __restrict__ b2,
    const float* __restrict__ g2, const float* __restrict__ be2,
    const float* __restrict__ w3, const float* __restrict__ b3,
    const float* __restrict__ g3, const float* __restrict__ be3,
    float* __restrict__ out)
{
    __shared__ float x28[TP][28];
    __shared__ float t1s[TP][64];
    __shared__ float in2[TP][128];
    __shared__ int sp_g[TP];
    __shared__ int sp_a[TP][4];
    __shared__ int sp_ga[TP][4];

    const int tid = threadIdx.x;
    const int blk = blockIdx.x;
    const int b   = blk / (SS / TP);
    const int s0  = (blk % (SS / TP)) * TP;

    if (tid < TP) {
        int p = tid;
        int s = s0 + p;
        int g = sample[b * SS + s];
        sp_g[p] = g;
        #pragma unroll
        for (int k = 0; k < 4; k++) {
            sp_a[p][k] = g_aidx[(b * SS + s) * 4 + k];
            int sa = g_saidx[(b * SS + s) * 4 + k];
            sp_ga[p][k] = sample[b * SS + sa];
        }
        #pragma unroll
        for (int k = 0; k < 3; k++) {
            x28[p][k]     = g_adist[(b * SS + s) * 4 + 1 + k];
            x28[p][6 + k] = g_sadist[(b * SS + s) * 4 + 1 + k];
        }
    }
    __syncthreads();

    for (int t = tid; t < TP * 22; t += 128) {
        int p = t / 22, w = t % 22;
        int ia, ib, ch;
        if (w < 3) {
            int pi = (w < 2) ? 1 : 2;
            int pj = (w == 0) ? 2 : 3;
            ia = sp_a[p][pi]; ib = sp_a[p][pj]; ch = 3 + w;
        } else if (w < 6) {
            int u = w - 3;
            int pi = (u < 2) ? 1 : 2;
            int pj = (u == 0) ? 2 : 3;
            ia = sp_ga[p][pi]; ib = sp_ga[p][pj]; ch = 9 + u;
        } else {
            int u = w - 6;
            int i = u >> 2, j = u & 3;
            ia = sp_a[p][i]; ib = sp_ga[p][j]; ch = 12 + u;
        }
        float4 pa = g_xyzw[b * NN + ia];
        float4 pb = g_xyzw[b * NN + ib];
        float dot = fmaf(pa.x, pb.x, fmaf(pa.y, pb.y, pa.z * pb.z));
        float d2 = fmaxf(pa.w + pb.w - 2.0f * dot, 1e-12f);
        x28[p][ch] = sqrtf(d2);
    }

    for (int t = tid; t < TP * 64; t += 128) {
        int p = t >> 6, c = t & 63;
        in2[p][c] = feature[(size_t)(b * NN + sp_g[p]) * IN_CH + c];
    }
    __syncthreads();

    const float invs = 1.0f / sqrtf(1.0f + 1e-5f);
    const int c  = tid & 63;
    const int pb = (tid >> 6) * 8;

    // layer 1: 28 -> 64 (7 float4 k-groups)
    {
        float acc[8];
        #pragma unroll
        for (int p = 0; p < 8; p++) acc[p] = b1[c];
        #pragma unroll
        for (int k4 = 0; k4 < 7; k4++) {
            float wa = w1[(4 * k4 + 0) * 64 + c];
            float wb = w1[(4 * k4 + 1) * 64 + c];
            float wc = w1[(4 * k4 + 2) * 64 + c];
            float wd = w1[(4 * k4 + 3) * 64 + c];
            #pragma unroll
            for (int p = 0; p < 8; p++) {
                float4 xv = reinterpret_cast<const float4*>(&x28[pb + p][0])[k4];
                acc[p] = fmaf(xv.x, wa, acc[p]);
                acc[p] = fmaf(xv.y, wb, acc[p]);
                acc[p] = fmaf(xv.z, wc, acc[p]);
                acc[p] = fmaf(xv.w, wd, acc[p]);
            }
        }
        float sc = g1[c] * invs, sh = be1[c];
        #pragma unroll
        for (int p = 0; p < 8; p++) {
            float v = fmaf(acc[p], sc, sh);
            t1s[pb + p][c] = (v >= 0.0f) ? v : 0.2f * v;
        }
    }
    __syncthreads();

    // layer 2: 64 -> 64 (16 float4 k-groups), output into in2[p][64..127]
    {
        float acc[8];
        #pragma unroll
        for (int p = 0; p < 8; p++) acc[p] = b2[c];
        #pragma unroll
        for (int k4 = 0; k4 < 16; k4++) {
            float wa = w2[(4 * k4 + 0) * 64 + c];
            float wb = w2[(4 * k4 + 1) * 64 + c];
            float wc = w2[(4 * k4 + 2) * 64 + c];
            float wd = w2[(4 * k4 + 3) * 64 + c];
            #pragma unroll
            for (int p = 0; p < 8; p++) {
                float4 xv = reinterpret_cast<const float4*>(&t1s[pb + p][0])[k4];
                acc[p] = fmaf(xv.x, wa, acc[p]);
                acc[p] = fmaf(xv.y, wb, acc[p]);
                acc[p] = fmaf(xv.z, wc, acc[p]);
                acc[p] = fmaf(xv.w, wd, acc[p]);
            }
        }
        float sc = g2[c] * invs, sh = be2[c];
        #pragma unroll
        for (int p = 0; p < 8; p++) {
            float v = fmaf(acc[p], sc, sh);
            in2[pb + p][64 + c] = (v >= 0.0f) ? v : 0.2f * v;
        }
    }
    __syncthreads();

    // layer 3: 128 -> 128 (32 float4 k-groups)
    {
        float acc[TP];
        #pragma unroll
        for (int p = 0; p < TP; p++) acc[p] = b3[tid];
        #pragma unroll 4
        for (int k4 = 0; k4 < 32; k4++) {
            float wa = w3[(4 * k4 + 0) * 128 + tid];
            float wb = w3[(4 * k4 + 1) * 128 + tid];
            float wc = w3[(4 * k4 + 2) * 128 + tid];
            float wd = w3[(4 * k4 + 3) * 128 + tid];
            #pragma unroll
            for (int p = 0; p < TP; p++) {
                float4 xv = reinterpret_cast<const float4*>(&in2[p][0])[k4];
                acc[p] = fmaf(xv.x, wa, acc[p]);
                acc[p] = fmaf(xv.y, wb, acc[p]);
                acc[p] = fmaf(xv.z, wc, acc[p]);
                acc[p] = fmaf(xv.w, wd, acc[p]);
            }
        }
        float sc = g3[tid] * invs, sh = be3[tid];
        const size_t obase = (size_t)BB * SS * 3;
        #pragma unroll
        for (int p = 0; p < TP; p++) {
            float v = fmaf(acc[p], sc, sh);
            v = (v >= 0.0f) ? v : 0.2f * v;
            out[obase + (size_t)((b * SS + s0 + p)) * OUT_CH + tid] = v;
        }
    }
}

// ---------------- launch ----------------
extern "C" void kernel_launch(void* const* d_in, const int* in_sizes, int n_in,
                              void* d_out, int out_size) {
    const float* xyz     = (const float*)d_in[0];
    const float* feature = (const float*)d_in[1];
    const int*   sample  = (const int*)d_in[2];
    const float* w1  = (const float*)d_in[3];
    const float* b1  = (const float*)d_in[4];
    const float* g1  = (const float*)d_in[5];
    const float* be1 = (const float*)d_in[6];
    const float* w2  = (const float*)d_in[7];
    const float* b2  = (const float*)d_in[8];
    const float* g2  = (const float*)d_in[9];
    const float* be2 = (const float*)d_in[10];
    const float* w3  = (const float*)d_in[11];
    const float* b3  = (const float*)d_in[12];
    const float* g3  = (const float*)d_in[13];
    const float* be3 = (const float*)d_in[14];
    float* out = (float*)d_out;

    k_prep_gather<<<(BB * (NN + SS) + 255) / 256, 256>>>(xyz, sample, out);

    k_sort_local<<<dim3(NN / 2048, BB), 1024>>>();   // k = 2..2048
    k_fin4k     <<<dim3(NN / 4096, BB), 1024>>>();   // k = 4096
    k_fin8k     <<<dim3(NN / 4096, BB), 1024>>>();   // k = 8192 (full stage, -> g_keys2)

    k_scatter_full<<<BB * NN / 256, 256>>>(sample);
    k_scatter_samp<<<BB * NN / 256, 256>>>();

    k_knn<<<dim3(SS / 8, BB, 2), 256>>>();

    k_fused<<<BB * SS / TP, 128>>>(feature, sample,
                                   w1, b1, g1, be1,
                                   w2, b2, g2, be2,
                                   w3, b3, g3, be3,
                                   out);
}

// round 15
// speedup vs baseline: 1.2707x; 1.0059x over previous
#include <cuda_runtime.h>
#include <math_constants.h>

#define BB 2
#define NN 8192
#define SS 4096
#define IN_CH 64
#define TRANS_CH 64
#define OUT_CH 128
#define TP 16         // sampled points per block in fused kernel

typedef unsigned long long u64;

// ---------------- device scratch (no cudaMalloc allowed) ----------------
__device__ float4 g_xyzw[BB * NN];      // x,y,z,|x|^2
__device__ u64    g_keys [BB * NN];     // (flipped z bits << 32) | idx-in-batch
__device__ u64    g_keys2[BB * NN];     // final sorted keys (double buffer)
__device__ int    g_srank[BB * NN];     // sorted pos -> s+1 (0 = not sampled)
__device__ int    g_ccnt[BB * 32];      // members per 256-chunk

// z-sorted full set + compacted sampled subset
__device__ float4 g_pfull[BB * NN];
__device__ float  g_zfull[BB * NN];
__device__ int    g_ofull[BB * NN];     // sorted pos -> original global id
__device__ float4 g_psamp[BB * SS];
__device__ float  g_zsamp[BB * SS];
__device__ int    g_osamp[BB * SS];     // sorted pos -> sample-space pos

// KNN results, keyed by SAMPLE-SPACE position s
__device__ int    g_aidx[BB * SS * 4];
__device__ float  g_adist[BB * SS * 4];
__device__ int    g_saidx[BB * SS * 4];
__device__ float  g_sadist[BB * SS * 4];

// ---------------- helpers ----------------
__device__ __forceinline__ void insert4f(float (&bd)[4], int (&bi)[4], float d, int j) {
    if (d >= bd[3]) return;
    if (d < bd[2]) {
        bd[3] = bd[2]; bi[3] = bi[2];
        if (d < bd[1]) {
            bd[2] = bd[1]; bi[2] = bi[1];
            if (d < bd[0]) {
                bd[1] = bd[0]; bi[1] = bi[0];
                bd[0] = d; bi[0] = j;
            } else { bd[1] = d; bi[1] = j; }
        } else { bd[2] = d; bi[2] = j; }
    } else { bd[3] = d; bi[3] = j; }
}

__device__ __forceinline__ u64 zkey(float z, unsigned idx) {
    unsigned bits = __float_as_uint(z);
    bits = (bits & 0x80000000u) ? ~bits : (bits | 0x80000000u);
    return ((u64)bits << 32) | idx;
}

// compare-exchange primitives (keys are UNIQUE -> min/max == network swap)
__device__ __forceinline__ void cmp_swap_pair(u64& lo, u64& hi, bool up) {
    u64 mn = lo < hi ? lo : hi;
    u64 mx = lo < hi ? hi : lo;
    lo = up ? mn : mx;
    hi = up ? mx : mn;
}
__device__ __forceinline__ u64 shfl_cmp(u64 v, int gi, int j, int k) {
    u64 o = __shfl_xor_sync(0xffffffffu, v, j);
    bool keepmin = (((gi & j) == 0) == ((gi & k) == 0));
    u64 mn = v < o ? v : o, mx = v < o ? o : v;
    return keepmin ? mn : mx;
}
__device__ __forceinline__ void reg_stage2(u64& a, u64& b, int ga, int k) {
    if (k >= 64) cmp_swap_pair(a, b, ((ga & k) == 0));
    int j0 = (k >> 1) > 16 ? 16 : (k >> 1);
    #pragma unroll
    for (int j = 16; j >= 1; j >>= 1) {
        if (j <= j0) {
            a = shfl_cmp(a, ga, j, k);
            b = shfl_cmp(b, ga + 32, j, k);
        }
    }
}

// warp butterfly merge of per-lane sorted top4 lists (entries disjoint across lanes)
__device__ __forceinline__ void warp_merge4(float (&bd)[4], int (&bi)[4]) {
    #pragma unroll
    for (int off = 16; off; off >>= 1) {
        float od[4]; int oi[4];
        #pragma unroll
        for (int k = 0; k < 4; k++) {
            od[k] = __shfl_xor_sync(0xffffffffu, bd[k], off);
            oi[k] = __shfl_xor_sync(0xffffffffu, bi[k], off);
        }
        #pragma unroll
        for (int k = 0; k < 4; k++) insert4f(bd, bi, od[k], oi[k]);
    }
}

// ---------------- K0: fused prep + sampled_xyz gather ----------------
__global__ void k_prep_gather(const float* __restrict__ xyz,
                              const int*   __restrict__ sample,
                              float* __restrict__ out) {
    int i = blockIdx.x * blockDim.x + threadIdx.x;
    if (i < BB * NN) {
        float x = xyz[3 * i], y = xyz[3 * i + 1], z = xyz[3 * i + 2];
        float sq = fmaf(x, x, fmaf(y, y, z * z));
        g_xyzw[i] = make_float4(x, y, z, sq);
        g_keys[i] = zkey(z, (unsigned)(i % NN));
    } else {
        int j = i - BB * NN;
        if (j >= BB * SS) return;
        int b = j / SS;
        int g = sample[j];
        const float* p = xyz + 3 * (b * NN + g);
        out[3 * j + 0] = p[0];
        out[3 * j + 1] = p[1];
        out[3 * j + 2] = p[2];
    }
}

// ---------------- sort stage A: local 2048-chunks, stages k=2..2048 ----------------
__global__ __launch_bounds__(1024) void k_sort_local() {
    __shared__ u64 sk[2048];
    const int base = blockIdx.x * 2048;
    u64* gk = g_keys + blockIdx.y * NN + base;
    const int t = threadIdx.x, w = t >> 5, l = t & 31;
    const int ia = (w << 6) + l, ib = ia + 32;
    const int ga = base + ia;

    u64 a = gk[ia], b = gk[ib];

    #pragma unroll
    for (int k = 2; k <= 64; k <<= 1)
        reg_stage2(a, b, ga, k);

    #pragma unroll
    for (int k = 128; k <= 2048; k <<= 1) {
        sk[ia] = a; sk[ib] = b;
        __syncthreads();
        for (int j = k >> 1; j >= 64; j >>= 1) {
            #pragma unroll
            for (int i = t; i < 2048; i += 1024) {
                int p = i ^ j;
                if (p > i) {
                    u64 x = sk[i], y = sk[p];
                    bool up = (((base + i) & k) == 0);
                    if ((x > y) == up) { sk[i] = y; sk[p] = x; }
                }
            }
            __syncthreads();
        }
        a = sk[ia]; b = sk[ib];
        reg_stage2(a, b, ga, k);
    }
    gk[ia] = a; gk[ib] = b;
}

// ---------------- sort stage B: 4096-window, stage k=4096 (in-place) ----------------
__global__ __launch_bounds__(1024) void k_fin4k() {
    const int k = 4096;
    __shared__ u64 sk[4096];
    const int base = blockIdx.x * 4096;
    u64* gk = g_keys + blockIdx.y * NN + base;
    const int t = threadIdx.x, w = t >> 5, l = t & 31;

    #pragma unroll
    for (int i = t; i < 4096; i += 1024) sk[i] = gk[i];
    __syncthreads();

    for (int j = 2048; j >= 64; j >>= 1) {
        #pragma unroll
        for (int i = t; i < 4096; i += 1024) {
            int p = i ^ j;
            if (p > i) {
                u64 x = sk[i], y = sk[p];
                bool up = (((base + i) & k) == 0);
                if ((x > y) == up) { sk[i] = y; sk[p] = x; }
            }
        }
        __syncthreads();
    }

    const int g0 = base + (w << 7) + l;
    u64 r0 = sk[(w << 7) + l];
    u64 r1 = sk[(w << 7) + l + 32];
    u64 r2 = sk[(w << 7) + l + 64];
    u64 r3 = sk[(w << 7) + l + 96];
    cmp_swap_pair(r0, r1, ((g0 & k) == 0));
    cmp_swap_pair(r2, r3, (((g0 + 64) & k) == 0));
    #pragma unroll
    for (int j = 16; j >= 1; j >>= 1) {
        r0 = shfl_cmp(r0, g0,      j, k);
        r1 = shfl_cmp(r1, g0 + 32, j, k);
        r2 = shfl_cmp(r2, g0 + 64, j, k);
        r3 = shfl_cmp(r3, g0 + 96, j, k);
    }
    gk[(w << 7) + l]      = r0;
    gk[(w << 7) + l + 32] = r1;
    gk[(w << 7) + l + 64] = r2;
    gk[(w << 7) + l + 96] = r3;
}

// ---------------- sort stage C: full k=8192 stage, g_keys -> g_keys2 ----------------
__global__ __launch_bounds__(1024) void k_fin8k() {
    const int k = 8192;
    __shared__ u64 sk[4096];
    const int base = blockIdx.x * 4096;          // window 0 or 1 (batch-local)
    const u64* gin  = g_keys  + blockIdx.y * NN;
    u64*       gout = g_keys2 + blockIdx.y * NN + base;
    const int t = threadIdx.x, w = t >> 5, l = t & 31;

    // j = 4096 pass: window 0 keeps min, window 1 keeps max
    #pragma unroll
    for (int i = t; i < 4096; i += 1024) {
        u64 a = gin[base + i];
        u64 b = gin[(base + i) ^ 4096];
        u64 mn = a < b ? a : b, mx = a < b ? b : a;
        sk[i] = (base == 0) ? mn : mx;
    }
    __syncthreads();

    for (int j = 2048; j >= 64; j >>= 1) {
        #pragma unroll
        for (int i = t; i < 4096; i += 1024) {
            int p = i ^ j;
            if (p > i) {
                u64 x = sk[i], y = sk[p];
                if (x > y) { sk[i] = y; sk[p] = x; }   // up = true everywhere
            }
        }
        __syncthreads();
    }

    const int g0 = base + (w << 7) + l;
    u64 r0 = sk[(w << 7) + l];
    u64 r1 = sk[(w << 7) + l + 32];
    u64 r2 = sk[(w << 7) + l + 64];
    u64 r3 = sk[(w << 7) + l + 96];
    cmp_swap_pair(r0, r1, true);
    cmp_swap_pair(r2, r3, true);
    #pragma unroll
    for (int j = 16; j >= 1; j >>= 1) {
        r0 = shfl_cmp(r0, g0,      j, k);
        r1 = shfl_cmp(r1, g0 + 32, j, k);
        r2 = shfl_cmp(r2, g0 + 64, j, k);
        r3 = shfl_cmp(r3, g0 + 96, j, k);
    }
    gout[(w << 7) + l]      = r0;
    gout[(w << 7) + l + 32] = r1;
    gout[(w << 7) + l + 64] = r2;
    gout[(w << 7) + l + 96] = r3;
}

// ---------------- compaction pass 1: full scatter + membership + chunk counts ----------------
__global__ __launch_bounds__(256) void k_scatter_full(const int* __restrict__ sample) {
    const int i = blockIdx.x * 256 + threadIdx.x;   // index in [0, BB*NN)
    const int b = i / NN;
    const int lane = threadIdx.x & 31, wid = threadIdx.x >> 5;

    u64 key = g_keys2[i];
    int g = (int)(key & 0xffffffffu);
    float4 v = g_xyzw[b * NN + g];
    g_pfull[i] = v;
    g_zfull[i] = v.z;
    g_ofull[i] = g;

    // membership: binary search in sorted sample[b]
    const int* sm = sample + b * SS;
    int lo = 0, hi = SS;
    while (lo < hi) { int mid = (lo + hi) >> 1; if (sm[mid] < g) lo = mid + 1; else hi = mid; }
    int s = (lo < SS && sm[lo] == g) ? (lo + 1) : 0;
    g_srank[i] = s;

    unsigned bal = __ballot_sync(0xffffffffu, s > 0);
    __shared__ int ws[8];
    if (lane == 0) ws[wid] = __popc(bal);
    __syncthreads();
    if (threadIdx.x == 0) {
        int tot = 0;
        #pragma unroll
        for (int w = 0; w < 8; w++) tot += ws[w];
        g_ccnt[blockIdx.x] = tot;
    }
}

// ---------------- compaction pass 2: rank + scatter sampled subset ----------------
__global__ __launch_bounds__(256) void k_scatter_samp() {
    const int i = blockIdx.x * 256 + threadIdx.x;
    const int b = i / NN;
    const int c = blockIdx.x & 31;                  // chunk within batch (32 per batch)
    const int lane = threadIdx.x & 31, wid = threadIdx.x >> 5;

    int s = g_srank[i];
    bool m = (s > 0);

    unsigned bal = __ballot_sync(0xffffffffu, m);
    int lrank = __popc(bal & ((1u << lane) - 1u));
    __shared__ int ws[8];
    __shared__ int coff;
    if (lane == 0) ws[wid] = __popc(bal);
    if (wid == 0) {                                 // prefix over preceding chunks
        int v = (lane < c) ? g_ccnt[b * 32 + lane] : 0;
        #pragma unroll
        for (int off = 16; off; off >>= 1) v += __shfl_xor_sync(0xffffffffu, v, off);
        if (lane == 0) coff = v;
    }
    __syncthreads();
    int woff = 0;
    #pragma unroll
    for (int w = 0; w < 8; w++) if (w < wid) woff += ws[w];

    if (m) {
        u64 key = g_keys2[i];
        int g = (int)(key & 0xffffffffu);
        int pos = coff + woff + lrank;
        float4 v = g_xyzw[b * NN + g];
        g_psamp[b * SS + pos] = v;
        g_zsamp[b * SS + pos] = v.z;
        g_osamp[b * SS + pos] = s - 1;
    }
}

// ---------------- KNN: two-phase window scan (round-14 proven) ----------------
__global__ __launch_bounds__(256) void k_knn() {
    const bool FULLV = (blockIdx.z == 0);
    const int b    = blockIdx.y;
    const int warp = threadIdx.x >> 5;
    const int lane = threadIdx.x & 31;
    const int r    = blockIdx.x * 8 + warp;      // rank in z-sorted sampled array

    const int M = FULLV ? NN : SS;
    const float4* pts = FULLV ? (g_pfull + b * NN) : (g_psamp + b * SS);
    const float*  zz  = FULLV ? (g_zfull + b * NN) : (g_zsamp + b * SS);
    const float4  qp  = g_psamp[b * SS + r];
    const float   qz  = qp.z;

    int start;
    if (FULLV) {
        int lo = 0, hi = NN;
        while (lo < hi) { int mid = (lo + hi) >> 1; if (zz[mid] < qz) lo = mid + 1; else hi = mid; }
        start = lo;
    } else {
        start = r;
    }

    float bd[4] = {CUDART_INF_F, CUDART_INF_F, CUDART_INF_F, CUDART_INF_F};
    int   bi[4] = {0, 0, 0, 0};

    // ---- phase 1: 256 candidates [start-128, start+128), 8 per lane ----
    const int p0 = start - 128;
    #pragma unroll
    for (int u = 0; u < 8; u++) {
        int idx = p0 + (u << 5) + lane;
        if (idx >= 0 && idx < M) {
            float4 c = pts[idx];
            float dot = fmaf(qp.x, c.x, fmaf(qp.y, c.y, qp.z * c.z));
            float d2  = fmaxf(qp.w + c.w - 2.0f * dot, 1e-12f);
            insert4f(bd, bi, d2, idx);
        }
    }
    warp_merge4(bd, bi);              // all lanes now hold exact top4 of the 256
    const float thr = bd[3];          // tight conservative radius^2

    // lanes != 0 restart with empty lists so the FINAL merge stays duplicate-free
    if (lane != 0) {
        #pragma unroll
        for (int k = 0; k < 4; k++) { bd[k] = CUDART_INF_F; bi[k] = 0; }
    }

    // ---- phase 2 right ----
    for (int base = start + 128; base < M; base += 64) {
        float dz = zz[base] - qz;
        if (dz * dz > thr) break;
        #pragma unroll
        for (int u = 0; u < 2; u++) {
            int idx = base + (u << 5) + lane;
            if (idx < M) {
                float4 c = pts[idx];
                float dot = fmaf(qp.x, c.x, fmaf(qp.y, c.y, qp.z * c.z));
                float d2  = fmaxf(qp.w + c.w - 2.0f * dot, 1e-12f);
                insert4f(bd, bi, d2, idx);
            }
        }
    }

    // ---- phase 2 left ----
    for (int base = start - 192; base + 64 > 0; base -= 64) {
        float dz = qz - zz[base + 63];
        if (dz * dz > thr) break;
        #pragma unroll
        for (int u = 0; u < 2; u++) {
            int idx = base + (u << 5) + lane;
            if (idx >= 0) {
                float4 c = pts[idx];
                float dot = fmaf(qp.x, c.x, fmaf(qp.y, c.y, qp.z * c.z));
                float d2  = fmaxf(qp.w + c.w - 2.0f * dot, 1e-12f);
                insert4f(bd, bi, d2, idx);
            }
        }
    }

    warp_merge4(bd, bi);

    if (lane == 0) {
        int s = g_osamp[b * SS + r];
        if (FULLV) {
            #pragma unroll
            for (int k = 0; k < 4; k++) {
                g_aidx [(b * SS + s) * 4 + k] = g_ofull[b * NN + bi[k]];
                g_adist[(b * SS + s) * 4 + k] = sqrtf(bd[k]);
            }
        } else {
            #pragma unroll
            for (int k = 0; k < 4; k++) {
                g_saidx [(b * SS + s) * 4 + k] = g_osamp[b * SS + bi[k]];
                g_sadist[(b * SS + s) * 4 + k] = sqrtf(bd[k]);
            }
        }
    }
}

// ---------------- fused 28-feature build + 3-layer MLP ----------------
// Layers 2/3 register-tiled (2x4 and 4x4) to cut smem crossbar traffic ~4x.
// Activation LDS.128 are warp-broadcast (same address across lanes);
// weight LDG are lane-consecutive (coalesced). Accumulation stays k-ascending
// per output -> bit-identical to previous rounds.
__global__ __launch_bounds__(128) void k_fused(
    const float* __restrict__ feature,
    const int*   __restrict__ sample,
    const float* __restrict__ w1, const float* __restrict__ b1,
    const float* __restrict__ g1, const float* __restrict__ be1,
    const float* __restrict__ w2, const float* __restrict__ b2,
    const float* __restrict__ g2, const float* __restrict__ be2,
    const float* __restrict__ w3, const float* __restrict__ b3,
    const float* __restrict__ g3, const float* __restrict__ be3,
    float* __restrict__ out)
{
    __shared__ float x28[TP][28];
    __shared__ float t1s[TP][64];
    __shared__ float in2[TP][128];
    __shared__ int sp_g[TP];
    __shared__ int sp_a[TP][4];
    __shared__ int sp_ga[TP][4];

    const int tid = threadIdx.x;
    const int blk = blockIdx.x;
    const int b   = blk / (SS / TP);
    const int s0  = (blk % (SS / TP)) * TP;

    if (tid < TP) {
        int p = tid;
        int s = s0 + p;
        int g = sample[b * SS + s];
        sp_g[p] = g;
        #pragma unroll
        for (int k = 0; k < 4; k++) {
            sp_a[p][k] = g_aidx[(b * SS + s) * 4 + k];
            int sa = g_saidx[(b * SS + s) * 4 + k];
            sp_ga[p][k] = sample[b * SS + sa];
        }
        #pragma unroll
        for (int k = 0; k < 3; k++) {
            x28[p][k]     = g_adist[(b * SS + s) * 4 + 1 + k];
            x28[p][6 + k] = g_sadist[(b * SS + s) * 4 + 1 + k];
        }
    }
    __syncthreads();

    for (int t = tid; t < TP * 22; t += 128) {
        int p = t / 22, w = t % 22;
        int ia, ib, ch;
        if (w < 3) {
            int pi = (w < 2) ? 1 : 2;
            int pj = (w == 0) ? 2 : 3;
            ia = sp_a[p][pi]; ib = sp_a[p][pj]; ch = 3 + w;
        } else if (w < 6) {
            int u = w - 3;
            int pi = (u < 2) ? 1 : 2;
            int pj = (u == 0) ? 2 : 3;
            ia = sp_ga[p][pi]; ib = sp_ga[p][pj]; ch = 9 + u;
        } else {
            int u = w - 6;
            int i = u >> 2, j = u & 3;
            ia = sp_a[p][i]; ib = sp_ga[p][j]; ch = 12 + u;
        }
        float4 pa = g_xyzw[b * NN + ia];
        float4 pb = g_xyzw[b * NN + ib];
        float dot = fmaf(pa.x, pb.x, fmaf(pa.y, pb.y, pa.z * pb.z));
        float d2 = fmaxf(pa.w + pb.w - 2.0f * dot, 1e-12f);
        x28[p][ch] = sqrtf(d2);
    }

    for (int t = tid; t < TP * 64; t += 128) {
        int p = t >> 6, c = t & 63;
        in2[p][c] = feature[(size_t)(b * NN + sp_g[p]) * IN_CH + c];
    }
    __syncthreads();

    const float invs = 1.0f / sqrtf(1.0f + 1e-5f);

    // ---- layer 1: 28 -> 64 (unchanged: 2 halves x 64 channels) ----
    {
        const int c  = tid & 63;
        const int pb = (tid >> 6) * 8;
        float acc[8];
        #pragma unroll
        for (int p = 0; p < 8; p++) acc[p] = b1[c];
        #pragma unroll
        for (int k4 = 0; k4 < 7; k4++) {
            float wa = w1[(4 * k4 + 0) * 64 + c];
            float wb = w1[(4 * k4 + 1) * 64 + c];
            float wc = w1[(4 * k4 + 2) * 64 + c];
            float wd = w1[(4 * k4 + 3) * 64 + c];
            #pragma unroll
            for (int p = 0; p < 8; p++) {
                float4 xv = reinterpret_cast<const float4*>(&x28[pb + p][0])[k4];
                acc[p] = fmaf(xv.x, wa, acc[p]);
                acc[p] = fmaf(xv.y, wb, acc[p]);
                acc[p] = fmaf(xv.z, wc, acc[p]);
                acc[p] = fmaf(xv.w, wd, acc[p]);
            }
        }
        float sc = g1[c] * invs, sh = be1[c];
        #pragma unroll
        for (int p = 0; p < 8; p++) {
            float v = fmaf(acc[p], sc, sh);
            t1s[pb + p][c] = (v >= 0.0f) ? v : 0.2f * v;
        }
    }
    __syncthreads();

    // ---- layer 2: 64 -> 64, tiled 2 channels x 4 points ----
    {
        const int c0 = (tid & 31) * 2;        // channel pair
        const int pp = (tid >> 5) * 4;        // point group
        float acc[2][4];
        #pragma unroll
        for (int c = 0; c < 2; c++)
            #pragma unroll
            for (int p = 0; p < 4; p++) acc[c][p] = b2[c0 + c];
        #pragma unroll
        for (int k4 = 0; k4 < 16; k4++) {
            float4 act[4];
            #pragma unroll
            for (int p = 0; p < 4; p++)
                act[p] = reinterpret_cast<const float4*>(&t1s[pp + p][0])[k4];
            #pragma unroll
            for (int kk = 0; kk < 4; kk++) {
                float2 wv = *reinterpret_cast<const float2*>(&w2[(4 * k4 + kk) * 64 + c0]);
                #pragma unroll
                for (int p = 0; p < 4; p++) {
                    float a = (kk == 0) ? act[p].x : (kk == 1) ? act[p].y : (kk == 2) ? act[p].z : act[p].w;
                    acc[0][p] = fmaf(a, wv.x, acc[0][p]);
                    acc[1][p] = fmaf(a, wv.y, acc[1][p]);
                }
            }
        }
        #pragma unroll
        for (int c = 0; c < 2; c++) {
            float sc = g2[c0 + c] * invs, sh = be2[c0 + c];
            #pragma unroll
            for (int p = 0; p < 4; p++) {
                float v = fmaf(acc[c][p], sc, sh);
                in2[pp + p][64 + c0 + c] = (v >= 0.0f) ? v : 0.2f * v;
            }
        }
    }
    __syncthreads();

    // ---- layer 3: 128 -> 128, tiled 4 channels x 4 points ----
    {
        const int c0 = (tid & 31) * 4;        // channel quad
        const int pp = (tid >> 5) * 4;        // point group
        float acc[4][4];
        #pragma unroll
        for (int c = 0; c < 4; c++) {
            float bv = b3[c0 + c];
            #pragma unroll
            for (int p = 0; p < 4; p++) acc[c][p] = bv;
        }
        #pragma unroll 2
        for (int k4 = 0; k4 < 32; k4++) {
            float4 act[4];
            #pragma unroll
            for (int p = 0; p < 4; p++)
                act[p] = reinterpret_cast<const float4*>(&in2[pp + p][0])[k4];
            #pragma unroll
            for (int kk = 0; kk < 4; kk++) {
                float4 wv = *reinterpret_cast<const float4*>(&w3[(4 * k4 + kk) * 128 + c0]);
                #pragma unroll
                for (int p = 0; p < 4; p++) {
                    float a = (kk == 0) ? act[p].x : (kk == 1) ? act[p].y : (kk == 2) ? act[p].z : act[p].w;
                    acc[0][p] = fmaf(a, wv.x, acc[0][p]);
                    acc[1][p] = fmaf(a, wv.y, acc[1][p]);
                    acc[2][p] = fmaf(a, wv.z, acc[2][p]);
                    acc[3][p] = fmaf(a, wv.w, acc[3][p]);
                }
            }
        }
        float sc[4], sh[4];
        #pragma unroll
        for (int c = 0; c < 4; c++) { sc[c] = g3[c0 + c] * invs; sh[c] = be3[c0 + c]; }
        const size_t obase = (size_t)BB * SS * 3;
        #pragma unroll
        for (int p = 0; p < 4; p++) {
            float4 res;
            float v0 = fmaf(acc[0][p], sc[0], sh[0]); res.x = (v0 >= 0.0f) ? v0 : 0.2f * v0;
            float v1 = fmaf(acc[1][p], sc[1], sh[1]); res.y = (v1 >= 0.0f) ? v1 : 0.2f * v1;
            float v2 = fmaf(acc[2][p], sc[2], sh[2]); res.z = (v2 >= 0.0f) ? v2 : 0.2f * v2;
            float v3 = fmaf(acc[3][p], sc[3], sh[3]); res.w = (v3 >= 0.0f) ? v3 : 0.2f * v3;
            *reinterpret_cast<float4*>(&out[obase + (size_t)((b * SS + s0 + pp + p)) * OUT_CH + c0]) = res;
        }
    }
}

// ---------------- launch ----------------
extern "C" void kernel_launch(void* const* d_in, const int* in_sizes, int n_in,
                              void* d_out, int out_size) {
    const float* xyz     = (const float*)d_in[0];
    const float* feature = (const float*)d_in[1];
    const int*   sample  = (const int*)d_in[2];
    const float* w1  = (const float*)d_in[3];
    const float* b1  = (const float*)d_in[4];
    const float* g1  = (const float*)d_in[5];
    const float* be1 = (const float*)d_in[6];
    const float* w2  = (const float*)d_in[7];
    const float* b2  = (const float*)d_in[8];
    const float* g2  = (const float*)d_in[9];
    const float* be2 = (const float*)d_in[10];
    const float* w3  = (const float*)d_in[11];
    const float* b3  = (const float*)d_in[12];
    const float* g3  = (const float*)d_in[13];
    const float* be3 = (const float*)d_in[14];
    float* out = (float*)d_out;

    k_prep_gather<<<(BB * (NN + SS) + 255) / 256, 256>>>(xyz, sample, out);

    k_sort_local<<<dim3(NN / 2048, BB), 1024>>>();   // k = 2..2048
    k_fin4k     <<<dim3(NN / 4096, BB), 1024>>>();   // k = 4096
    k_fin8k     <<<dim3(NN / 4096, BB), 1024>>>();   // k = 8192 (full stage, -> g_keys2)

    k_scatter_full<<<BB * NN / 256, 256>>>(sample);
    k_scatter_samp<<<BB * NN / 256, 256>>>();

    k_knn<<<dim3(SS / 8, BB, 2), 256>>>();

    k_fused<<<BB * SS / TP, 128>>>(feature, sample,
                                   w1, b1, g1, be1,
                                   w2, b2, g2, be2,
                                   w3, b3, g3, be3,
                                   out);
}